// round 13
// baseline (speedup 1.0000x reference)
#include <cuda_runtime.h>
#include <cuda_fp16.h>
#include <cstdint>
#include <cstddef>

#define NP 50000
#define NL 10000
#define H  128
#define D  16
#define NLAYER 4
#define EPP 500000
#define ELP 100000
#define EPL 100000
#define ETOT (EPP + ELP + EPL)
#define NCNT (2 * NP + NL)
#define NBIN 512
#define CH0 49
#define CH1 49
#define CH2 10
#define CHT (CH0 + CH1 + CH2)

// ---------------- scratch (device globals; no runtime allocation) ----------------
__device__ float  g_xpA[NP * H];
__device__ float  g_xpB[NP * H];
__device__ float  g_xlA[NL * H];
__device__ float  g_xlB[NL * H];
__device__ __align__(16) __half g_xph[NP * H];
__device__ __align__(16) __half g_xlh[NL * H];
__device__ __align__(16) __half g_Wh[(size_t)48 * 128 * 128];
__device__ __align__(16) __half g_Pp[(size_t)NP * 8 * H];   // f|s pairs adjacent (+0/+H)
__device__ __align__(16) __half g_Pl[(size_t)NL * 4 * H];
__device__ float  g_agg_pp[NP * H];
__device__ float  g_agg_lp[NP * H];
__device__ float  g_agg_pl[NL * H];
// fp16 interleaved LUT: Th[lt][bin][col] = (T(bin), T(bin+1))
__device__ __align__(16) __half2 g_Th[(size_t)12 * NBIN * 256];
__device__ int    g_cnt[NCNT];
__device__ int    g_off[NCNT + 3];
__device__ int    g_cur[NCNT];
__device__ int    g_ssrc[ETOT];
__device__ float  g_su[ETOT];
__device__ int    g_chunksum[CHT];
__device__ int    g_chunkbase[CHT];

// ---------------- small helpers ----------------
__device__ __forceinline__ uint32_t smem_u32(const void* p) {
    uint32_t a;
    asm("{ .reg .u64 t; cvta.to.shared.u64 t, %1; cvt.u32.u64 %0, t; }" : "=r"(a) : "l"(p));
    return a;
}
__device__ __forceinline__ void ldsm_x4(uint32_t& r0, uint32_t& r1, uint32_t& r2, uint32_t& r3,
                                        uint32_t addr) {
    asm volatile("ldmatrix.sync.aligned.m8n8.x4.shared.b16 {%0,%1,%2,%3}, [%4];"
                 : "=r"(r0), "=r"(r1), "=r"(r2), "=r"(r3) : "r"(addr));
}
__device__ __forceinline__ void block_reduce_2(float& s, float& q, float* shbuf)
{
    unsigned m = 0xffffffffu;
    #pragma unroll
    for (int o = 16; o > 0; o >>= 1) {
        s += __shfl_down_sync(m, s, o);
        q += __shfl_down_sync(m, q, o);
    }
    int lane = threadIdx.x & 31, wid = threadIdx.x >> 5;
    if (lane == 0) { shbuf[wid] = s; shbuf[4 + wid] = q; }
    __syncthreads();
    s = shbuf[0] + shbuf[1] + shbuf[2] + shbuf[3];
    q = shbuf[4] + shbuf[5] + shbuf[6] + shbuf[7];
    __syncthreads();
}
__device__ __forceinline__ float sig_tanh(float x) {
    float t;
    asm("tanh.approx.f32 %0, %1;" : "=f"(t) : "f"(x * 0.5f));
    return 0.5f * t + 0.5f;
}
__device__ __forceinline__ float softplus_f(float x) {
    return fmaxf(x, 0.f) + __logf(1.0f + __expf(-fabsf(x)));
}
__device__ __forceinline__ float4 h4f(uint2 v) {
    __half2 a = *(__half2*)&v.x;
    __half2 b = *(__half2*)&v.y;
    float2 fa = __half22float2(a);
    float2 fb = __half22float2(b);
    return make_float4(fa.x, fa.y, fb.x, fb.y);
}
__device__ __forceinline__ float4 cg_ln_relu(float4 a, float4 lw, float4 lb)
{
    float s = a.x + a.y + a.z + a.w;
    float q = a.x * a.x + a.y * a.y + a.z * a.z + a.w * a.w;
    #pragma unroll
    for (int o = 16; o > 0; o >>= 1) {
        s += __shfl_xor_sync(0xffffffffu, s, o);
        q += __shfl_xor_sync(0xffffffffu, q, o);
    }
    float mean = s * (1.0f / H);
    float var = q * (1.0f / H) - mean * mean;
    float r = rsqrtf(var + 1e-5f);
    float4 y;
    y.x = fmaxf((a.x - mean) * r * lw.x + lb.x, 0.f);
    y.y = fmaxf((a.y - mean) * r * lw.y + lb.y, 0.f);
    y.z = fmaxf((a.z - mean) * r * lw.z + lb.z, 0.f);
    y.w = fmaxf((a.w - mean) * r * lw.w + lb.w, 0.f);
    return y;
}

// ---------------- CSR build ----------------
__global__ void hist_all(const int* __restrict__ ei_pp, const int* __restrict__ ei_lp,
                         const int* __restrict__ ei_pl, int* __restrict__ cnt)
{
    int idx = blockIdx.x * blockDim.x + threadIdx.x;
    if (idx >= ETOT) return;
    if (idx < EPP) {
        atomicAdd(&cnt[ei_pp[EPP + idx]], 1);
    } else if (idx < EPP + ELP) {
        int e = idx - EPP;
        atomicAdd(&cnt[NP + ei_lp[ELP + e]], 1);
    } else {
        int e = idx - EPP - ELP;
        atomicAdd(&cnt[2 * NP + ei_pl[EPL + e]], 1);
    }
}

__global__ __launch_bounds__(1024) void scanA(const int* __restrict__ cnt,
                                              int* __restrict__ off,
                                              int* __restrict__ chunksum)
{
    __shared__ int s[1024];
    int bid = blockIdx.x;
    const int* cbase; int* obase; int N; int c;
    if (bid < CH0)            { cbase = cnt;          obase = off;              N = NP; c = bid; }
    else if (bid < CH0 + CH1) { cbase = cnt + NP;     obase = off + NP + 1;     N = NP; c = bid - CH0; }
    else                      { cbase = cnt + 2 * NP; obase = off + 2 * NP + 2; N = NL; c = bid - CH0 - CH1; }
    int tid = threadIdx.x;
    int i = c * 1024 + tid;
    int v = (i < N) ? cbase[i] : 0;
    s[tid] = v;
    __syncthreads();
    #pragma unroll
    for (int o = 1; o < 1024; o <<= 1) {
        int t = (tid >= o) ? s[tid - o] : 0;
        __syncthreads();
        s[tid] += t;
        __syncthreads();
    }
    if (i < N) obase[i] = s[tid] - v;
    if (tid == 1023) chunksum[bid] = s[1023];
}

__global__ void scanB(const int* __restrict__ chunksum, int* __restrict__ chunkbase,
                      int* __restrict__ off)
{
    int t = threadIdx.x;
    if (t == 0) {
        int b = 0;
        for (int c = 0; c < CH0; ++c) { chunkbase[c] = b; b += chunksum[c]; }
        off[NP] = b;
    } else if (t == 1) {
        int b = 0;
        for (int c = 0; c < CH1; ++c) { chunkbase[CH0 + c] = b; b += chunksum[CH0 + c]; }
        off[NP + 1 + NP] = b;
    } else if (t == 2) {
        int b = 0;
        for (int c = 0; c < CH2; ++c) { chunkbase[CH0 + CH1 + c] = b; b += chunksum[CH0 + CH1 + c]; }
        off[2 * NP + 2 + NL] = b;
    }
}

__global__ __launch_bounds__(1024) void scanC(int* __restrict__ off,
                                              const int* __restrict__ chunkbase,
                                              int* __restrict__ cur)
{
    int bid = blockIdx.x;
    int* obase; int* curb; int N; int c;
    if (bid < CH0)            { obase = off;              curb = cur;          N = NP; c = bid; }
    else if (bid < CH0 + CH1) { obase = off + NP + 1;     curb = cur + NP;     N = NP; c = bid - CH0; }
    else                      { obase = off + 2 * NP + 2; curb = cur + 2 * NP; N = NL; c = bid - CH0 - CH1; }
    int i = c * 1024 + threadIdx.x;
    if (i < N) {
        int v = obase[i] + chunkbase[bid];
        obase[i] = v;
        curb[i] = v;
    }
}

__global__ void scatter_all(const int* __restrict__ ei_pp, const float* __restrict__ ea_pp,
                            const int* __restrict__ ei_lp, const float* __restrict__ ea_lp,
                            const int* __restrict__ ei_pl, const float* __restrict__ ea_pl,
                            int* __restrict__ cur, int* __restrict__ ssrc,
                            float* __restrict__ su)
{
    const float usc = (float)NBIN / 8.0f;
    int idx = blockIdx.x * blockDim.x + threadIdx.x;
    if (idx >= ETOT) return;
    if (idx < EPP) {
        int e = idx;
        int d = ei_pp[EPP + e];
        int p = atomicAdd(&cur[d], 1);
        ssrc[p] = ei_pp[e];
        su[p] = ea_pp[e] * usc;
    } else if (idx < EPP + ELP) {
        int e = idx - EPP;
        int d = ei_lp[ELP + e];
        int p = EPP + atomicAdd(&cur[NP + d], 1);
        ssrc[p] = ei_lp[e];
        su[p] = ea_lp[e] * usc;
    } else {
        int e = idx - EPP - ELP;
        int d = ei_pl[EPL + e];
        int p = EPP + ELP + atomicAdd(&cur[2 * NP + d], 1);
        ssrc[p] = ei_pl[e];
        su[p] = ea_pl[e] * usc;
    }
}

// ---------------- LUT build: fp16 interleaved (lo, hi) ----------------
__global__ __launch_bounds__(256) void lut_build(
    const float* __restrict__ Wf, const float* __restrict__ Ws, __half2* __restrict__ Th)
{
    int b = blockIdx.x;
    int lt = blockIdx.y;
    int j = threadIdx.x;
    const float step = 8.0f / 15.0f;
    const float coeff = -0.5f / (step * step);
    const float* W = (j < 128 ? Wf : Ws) + ((size_t)lt * 272 + 256) * H + (j & 127);
    float accL = 0.f, accH = 0.f;
    float dL = (float)b * (8.0f / (float)NBIN);
    float dH = (float)(b + 1) * (8.0f / (float)NBIN);
    #pragma unroll
    for (int k = 0; k < 16; ++k) {
        float w = W[(size_t)k * H];
        float dltL = dL - (float)k * step;
        float dltH = dH - (float)k * step;
        accL += __expf(coeff * dltL * dltL) * w;
        accH += __expf(coeff * dltH * dltH) * w;
    }
    Th[((size_t)lt * NBIN + b) * 256 + j] = __floats2half2_rn(accL, accH);
}

// ---------------- fp16 weight pre-convert ----------------
__global__ __launch_bounds__(128) void wconv(
    const float* __restrict__ Wf, const float* __restrict__ Ws, __half* __restrict__ Wh)
{
    const int bmap[12] = {0, 0, 0, 0, 1, 1, 2, 2, 1, 1, 2, 2};
    const int rmap[12] = {0, 0, 128, 128, 0, 0, 128, 128, 128, 128, 0, 0};
    const int fmap[12] = {1, 0, 1, 0, 1, 0, 1, 0, 1, 0, 1, 0};
    int ls = blockIdx.x;
    int layer = ls / 12, s = ls % 12;
    int k = blockIdx.y;
    int n = threadIdx.x;
    const float* base = fmap[s] ? Wf : Ws;
    float v = base[((size_t)(layer * 3 + bmap[s]) * 272 + rmap[s] + k) * H + n];
    Wh[((size_t)ls * 128 + n) * 128 + k] = __float2half(v);
}

// ---------------- merged initial embedding ----------------
__global__ __launch_bounds__(128) void embed_kernel(
    const float* __restrict__ xp, const float* __restrict__ Wp, const float* __restrict__ bp,
    const float* __restrict__ xl, const float* __restrict__ Wl, const float* __restrict__ bl,
    float* __restrict__ outp, float* __restrict__ outl,
    __half* __restrict__ outph, __half* __restrict__ outlh)
{
    int i = blockIdx.x;
    int j = threadIdx.x;
    const float *x, *W, *b; float* o; __half* oh; int r;
    if (i < NP) { x = xp; W = Wp; b = bp; o = outp; oh = outph; r = i; }
    else        { x = xl; W = Wl; b = bl; o = outl; oh = outlh; r = i - NP; }
    const float* xr = x + (size_t)r * 6;
    float acc = b[j];
    #pragma unroll
    for (int k = 0; k < 6; ++k) acc += xr[k] * W[k * H + j];
    o[(size_t)r * H + j] = acc;
    oh[(size_t)r * H + j] = __float2half(acc);
}

// ---------------- pipelined fp16 mma GEMM with ldmatrix ----------------
#define APH 72
#define ASTH (128 * APH)
#define BSTH (128 * APH)
#define STGH (ASTH + BSTH)
#define SMEM_MMA_BYTES (2 * STGH * 2)

__global__ __launch_bounds__(256, 2) void proj_mma(
    const __half* __restrict__ Xph, const __half* __restrict__ Xlh,
    const __half* __restrict__ Wh,
    __half* __restrict__ outP, __half* __restrict__ outL)
{
    int slice = blockIdx.y;
    const __half* Xh; __half* out; int N, outStride, col;
    if (slice < 8) { Xh = Xph; out = outP; N = NP; outStride = 8 * H; col = slice; }
    else           { Xh = Xlh; out = outL; N = NL; outStride = 4 * H; col = slice - 8; }
    int m0 = blockIdx.x * 128;
    if (m0 >= N) return;

    extern __shared__ __half smh[];
    uint32_t smb = smem_u32(smh);
    const __half* Whs = Wh + (size_t)slice * 128 * 128;
    int tid = threadIdx.x;
    int lane = tid & 31, warp = tid >> 5;
    int g = lane >> 2, t = lane & 3;

    auto load_stage = [&](int chunk, int s) {
        int kb = chunk * 64;
        uint32_t abase = smb + (uint32_t)(s * STGH) * 2u;
        uint32_t bbase = abase + (uint32_t)ASTH * 2u;
        #pragma unroll
        for (int i = 0; i < 4; ++i) {
            int idx = tid + i * 256;
            int r = idx >> 3, c8 = (idx & 7) * 8;
            uint32_t dst = abase + (uint32_t)(r * APH + c8) * 2u;
            const __half* src = Xh + (size_t)(m0 + r) * H + kb + c8;
            int sz = (m0 + r < N) ? 16 : 0;
            asm volatile("cp.async.cg.shared.global [%0], [%1], 16, %2;"
                         :: "r"(dst), "l"(src), "r"(sz));
        }
        #pragma unroll
        for (int i = 0; i < 4; ++i) {
            int idx = tid + i * 256;
            int n = idx >> 3, k8 = (idx & 7) * 8;
            uint32_t dst = bbase + (uint32_t)(n * APH + k8) * 2u;
            const __half* src = Whs + (size_t)n * 128 + kb + k8;
            asm volatile("cp.async.cg.shared.global [%0], [%1], 16;"
                         :: "r"(dst), "l"(src));
        }
        asm volatile("cp.async.commit_group;" ::: "memory");
    };

    load_stage(0, 0);
    load_stage(1, 1);

    int wm = warp >> 2;
    int wn = warp & 3;
    int mbase = wm * 64;
    int nbase = wn * 32;

    int a_row = lane & 15;
    int a_kh = (lane >> 4) * 8;
    int b_nrow = (lane >> 4) * 8 + (lane & 7);
    int b_kh = ((lane >> 3) & 1) * 8;

    float d[4][4][4];
    #pragma unroll
    for (int i = 0; i < 4; ++i)
        #pragma unroll
        for (int j = 0; j < 4; ++j)
            #pragma unroll
            for (int q = 0; q < 4; ++q) d[i][j][q] = 0.f;

    #pragma unroll
    for (int c = 0; c < 2; ++c) {
        if (c == 0) asm volatile("cp.async.wait_group 1;" ::: "memory");
        else        asm volatile("cp.async.wait_group 0;" ::: "memory");
        __syncthreads();

        uint32_t abase = smb + (uint32_t)(c * STGH) * 2u;
        uint32_t bbase = abase + (uint32_t)ASTH * 2u;

        #pragma unroll
        for (int ks = 0; ks < 4; ++ks) {
            int kbl = ks * 16;
            uint32_t a[4][4];
            #pragma unroll
            for (int i = 0; i < 4; ++i) {
                uint32_t addr = abase +
                    (uint32_t)((mbase + i * 16 + a_row) * APH + kbl + a_kh) * 2u;
                ldsm_x4(a[i][0], a[i][1], a[i][2], a[i][3], addr);
            }
            uint32_t b[4][2];
            #pragma unroll
            for (int jp = 0; jp < 2; ++jp) {
                uint32_t addr = bbase +
                    (uint32_t)((nbase + jp * 16 + b_nrow) * APH + kbl + b_kh) * 2u;
                ldsm_x4(b[2 * jp][0], b[2 * jp][1], b[2 * jp + 1][0], b[2 * jp + 1][1], addr);
            }
            #pragma unroll
            for (int i = 0; i < 4; ++i)
                #pragma unroll
                for (int j = 0; j < 4; ++j) {
                    asm volatile(
                        "mma.sync.aligned.m16n8k16.row.col.f32.f16.f16.f32 "
                        "{%0,%1,%2,%3}, {%4,%5,%6,%7}, {%8,%9}, {%0,%1,%2,%3};"
                        : "+f"(d[i][j][0]), "+f"(d[i][j][1]), "+f"(d[i][j][2]), "+f"(d[i][j][3])
                        : "r"(a[i][0]), "r"(a[i][1]), "r"(a[i][2]), "r"(a[i][3]),
                          "r"(b[j][0]), "r"(b[j][1]));
                }
        }
    }

    size_t colbase = (size_t)col * H;
    #pragma unroll
    for (int i = 0; i < 4; ++i) {
        int gr0 = m0 + mbase + i * 16 + g;
        int gr1 = gr0 + 8;
        #pragma unroll
        for (int j = 0; j < 4; ++j) {
            int gc = nbase + j * 8 + t * 2;
            if (gr0 < N)
                *(__half2*)(out + (size_t)gr0 * outStride + colbase + gc) =
                    __floats2half2_rn(d[i][j][0], d[i][j][1]);
            if (gr1 < N)
                *(__half2*)(out + (size_t)gr1 * outStride + colbase + gc) =
                    __floats2half2_rn(d[i][j][2], d[i][j][3]);
        }
    }
}

// ---------------- merged CSR edge kernel: double-buffered 4-edge batches ----------
struct EdgeArgs {
    const int*    off[3];
    const int*    ssrc[3];
    const float*  su[3];
    const __half2* T[3];
    const __half* Pd[3]; int dstr[3];
    const __half* Ps[3]; int sstr[3];
    const float*  bfp[3];
    const float*  bsp[3];
    float*        agg[3];
};

struct EBatch {
    uint2 rf[4], rs[4];
    float u[4];
};

__device__ __forceinline__ void load_batch(
    EBatch& b, const int* __restrict__ ssrc, const float* __restrict__ su,
    const __half* __restrict__ Ps, int sstr, int j0, int p, int pe)
{
    #pragma unroll
    for (int q = 0; q < 4; ++q) {
        int i = min(p + q, pe);
        int s = ssrc[i];
        b.u[q] = su[i];
        const __half* qp = Ps + (size_t)s * sstr + j0;
        b.rf[q] = *(const uint2*)(qp);
        b.rs[q] = *(const uint2*)(qp + H);
    }
}

__device__ __forceinline__ void edge_math(
    float4 fsv, float4 ssv, float u, const __half2* __restrict__ T, int j0,
    float fd0, float fd1, float fd2, float fd3,
    float sd0, float sd1, float sd2, float sd3,
    float& a0, float& a1, float& a2, float& a3, bool valid)
{
    int b = min((int)u, NBIN - 1);
    float w = u - (float)b;
    const __half2* Tb = T + (size_t)b * 256 + j0;
    uint4 fv = *(const uint4*)(Tb);
    uint4 sv = *(const uint4*)(Tb + 128);
    float2 f0p = __half22float2(*(__half2*)&fv.x);
    float2 f1p = __half22float2(*(__half2*)&fv.y);
    float2 f2p = __half22float2(*(__half2*)&fv.z);
    float2 f3p = __half22float2(*(__half2*)&fv.w);
    float2 s0p = __half22float2(*(__half2*)&sv.x);
    float2 s1p = __half22float2(*(__half2*)&sv.y);
    float2 s2p = __half22float2(*(__half2*)&sv.z);
    float2 s3p = __half22float2(*(__half2*)&sv.w);

    float f0 = fd0 + fsv.x + f0p.x + w * (f0p.y - f0p.x);
    float f1 = fd1 + fsv.y + f1p.x + w * (f1p.y - f1p.x);
    float f2 = fd2 + fsv.z + f2p.x + w * (f2p.y - f2p.x);
    float f3 = fd3 + fsv.w + f3p.x + w * (f3p.y - f3p.x);
    float s0 = sd0 + ssv.x + s0p.x + w * (s0p.y - s0p.x);
    float s1 = sd1 + ssv.y + s1p.x + w * (s1p.y - s1p.x);
    float s2 = sd2 + ssv.z + s2p.x + w * (s2p.y - s2p.x);
    float s3 = sd3 + ssv.w + s3p.x + w * (s3p.y - s3p.x);

    if (valid) {
        a0 += sig_tanh(f0) * softplus_f(s0);
        a1 += sig_tanh(f1) * softplus_f(s1);
        a2 += sig_tanh(f2) * softplus_f(s2);
        a3 += sig_tanh(f3) * softplus_f(s3);
    }
}

__global__ __launch_bounds__(256) void edge_all(EdgeArgs ea)
{
    int w = blockIdx.x * 8 + (threadIdx.x >> 5);
    int lane = threadIdx.x & 31;
    int j0 = lane * 4;

    int t, n;
    if (w < NP)               { t = 0; n = w; }
    else if (w < 2 * NP)      { t = 1; n = w - NP; }
    else if (w < 2 * NP + NL) { t = 2; n = w - 2 * NP; }
    else return;

    const int* off = ea.off[t];
    int p0 = off[n], p1 = off[n + 1];

    float4 bf4 = *(const float4*)(ea.bfp[t] + j0);
    float4 bs4 = *(const float4*)(ea.bsp[t] + j0);
    const __half* pd = ea.Pd[t] + (size_t)n * ea.dstr[t] + j0;
    float4 fdv = h4f(*(const uint2*)(pd));
    float4 sdv = h4f(*(const uint2*)(pd + H));
    float fd0 = fdv.x + bf4.x, fd1 = fdv.y + bf4.y, fd2 = fdv.z + bf4.z, fd3 = fdv.w + bf4.w;
    float sd0 = sdv.x + bs4.x, sd1 = sdv.y + bs4.y, sd2 = sdv.z + bs4.z, sd3 = sdv.w + bs4.w;

    const __half* Ps = ea.Ps[t];
    int sstr = ea.sstr[t];
    const int* ssrc = ea.ssrc[t];
    const float* su = ea.su[t];
    const __half2* T = ea.T[t];

    float a0 = 0.f, a1 = 0.f, a2 = 0.f, a3 = 0.f;

    if (p0 < p1) {
        int pe = p1 - 1;
        EBatch cur, nxt;
        load_batch(cur, ssrc, su, Ps, sstr, j0, p0, pe);
        for (int p = p0; p < p1; p += 4) {
            if (p + 4 < p1) load_batch(nxt, ssrc, su, Ps, sstr, j0, p + 4, pe);
            edge_math(h4f(cur.rf[0]), h4f(cur.rs[0]), cur.u[0], T, j0,
                      fd0, fd1, fd2, fd3, sd0, sd1, sd2, sd3, a0, a1, a2, a3, true);
            edge_math(h4f(cur.rf[1]), h4f(cur.rs[1]), cur.u[1], T, j0,
                      fd0, fd1, fd2, fd3, sd0, sd1, sd2, sd3, a0, a1, a2, a3, p + 1 < p1);
            edge_math(h4f(cur.rf[2]), h4f(cur.rs[2]), cur.u[2], T, j0,
                      fd0, fd1, fd2, fd3, sd0, sd1, sd2, sd3, a0, a1, a2, a3, p + 2 < p1);
            edge_math(h4f(cur.rf[3]), h4f(cur.rs[3]), cur.u[3], T, j0,
                      fd0, fd1, fd2, fd3, sd0, sd1, sd2, sd3, a0, a1, a2, a3, p + 3 < p1);
            cur = nxt;
        }
    }
    *(float4*)(ea.agg[t] + (size_t)n * H + j0) = make_float4(a0, a1, a2, a3);
}

// ---------------- merged node epilogue ----------------
__global__ __launch_bounds__(256) void node_update(
    const float* __restrict__ xp_in, const float* __restrict__ agg_pp,
    const float* __restrict__ agg_lp,
    const float* __restrict__ xl_in, const float* __restrict__ agg_pl,
    const float* __restrict__ bn_w, const float* __restrict__ bn_b,
    const float* __restrict__ ln_w, const float* __restrict__ ln_b, int l,
    float* __restrict__ xp_out, float* __restrict__ xl_out,
    __half* __restrict__ xph_out, __half* __restrict__ xlh_out)
{
    int w = blockIdx.x * 8 + (threadIdx.x >> 5);
    int lane = threadIdx.x & 31;
    int j0 = lane * 4;
    const float bnf = rsqrtf(1.0f + 1e-5f);

    if (w < NP) {
        size_t off = (size_t)w * H + j0;
        float4 x = *(const float4*)(xp_in + off);

        size_t pb0 = (size_t)(l * 3 + 0) * H + j0;
        float4 bw = *(const float4*)(bn_w + pb0);
        float4 bb = *(const float4*)(bn_b + pb0);
        float4 lw = *(const float4*)(ln_w + pb0);
        float4 lb = *(const float4*)(ln_b + pb0);
        float4 g = *(const float4*)(agg_pp + off);
        float4 a;
        a.x = g.x * (bw.x * bnf) + bb.x + x.x;
        a.y = g.y * (bw.y * bnf) + bb.y + x.y;
        a.z = g.z * (bw.z * bnf) + bb.z + x.z;
        a.w = g.w * (bw.w * bnf) + bb.w + x.w;
        float4 y1 = cg_ln_relu(a, lw, lb);

        size_t pb1 = (size_t)(l * 3 + 1) * H + j0;
        bw = *(const float4*)(bn_w + pb1);
        bb = *(const float4*)(bn_b + pb1);
        lw = *(const float4*)(ln_w + pb1);
        lb = *(const float4*)(ln_b + pb1);
        g = *(const float4*)(agg_lp + off);
        a.x = g.x * (bw.x * bnf) + bb.x + x.x;
        a.y = g.y * (bw.y * bnf) + bb.y + x.y;
        a.z = g.z * (bw.z * bnf) + bb.z + x.z;
        a.w = g.w * (bw.w * bnf) + bb.w + x.w;
        float4 y2 = cg_ln_relu(a, lw, lb);

        float4 r;
        r.x = y1.x + y2.x + 2.f * x.x;
        r.y = y1.y + y2.y + 2.f * x.y;
        r.z = y1.z + y2.z + 2.f * x.z;
        r.w = y1.w + y2.w + 2.f * x.w;
        *(float4*)(xp_out + off) = r;
        *(__half2*)(xph_out + off) = __floats2half2_rn(r.x, r.y);
        *(__half2*)(xph_out + off + 2) = __floats2half2_rn(r.z, r.w);
    } else if (w < NP + NL) {
        int i = w - NP;
        size_t off = (size_t)i * H + j0;
        float4 x = *(const float4*)(xl_in + off);
        size_t pb2 = (size_t)(l * 3 + 2) * H + j0;
        float4 bw = *(const float4*)(bn_w + pb2);
        float4 bb = *(const float4*)(bn_b + pb2);
        float4 lw = *(const float4*)(ln_w + pb2);
        float4 lb = *(const float4*)(ln_b + pb2);
        float4 g = *(const float4*)(agg_pl + off);
        float4 a;
        a.x = g.x * (bw.x * bnf) + bb.x + x.x;
        a.y = g.y * (bw.y * bnf) + bb.y + x.y;
        a.z = g.z * (bw.z * bnf) + bb.z + x.z;
        a.w = g.w * (bw.w * bnf) + bb.w + x.w;
        float4 y = cg_ln_relu(a, lw, lb);
        float4 r;
        r.x = y.x + x.x; r.y = y.y + x.y; r.z = y.z + x.z; r.w = y.w + x.w;
        *(float4*)(xl_out + off) = r;
        *(__half2*)(xlh_out + off) = __floats2half2_rn(r.x, r.y);
        *(__half2*)(xlh_out + off + 2) = __floats2half2_rn(r.z, r.w);
    }
}

// ---------------- final: LN(xp) @ fc_w + fc_b ----------------
__global__ __launch_bounds__(128) void final_kernel(
    const float* __restrict__ xp,
    const float* __restrict__ lnw, const float* __restrict__ lnb,
    const float* __restrict__ fcw, const float* __restrict__ fcb,
    float* __restrict__ out)
{
    __shared__ float sh[8];
    __shared__ float yb[H];
    __shared__ float part[4][21];
    int i = blockIdx.x, j = threadIdx.x;
    float x = xp[(size_t)i * H + j];
    float s = x, q = x * x;
    block_reduce_2(s, q, sh);
    float mean = s * (1.0f / H);
    float var = q * (1.0f / H) - mean * mean;
    yb[j] = (x - mean) * rsqrtf(var + 1e-5f) * lnw[j] + lnb[j];
    __syncthreads();
    if (j < 84) {
        int c = j % 21, qq = j / 21;
        float acc = 0.f;
        #pragma unroll
        for (int t = 0; t < 32; ++t) acc += yb[qq * 32 + t] * fcw[(qq * 32 + t) * 21 + c];
        part[qq][c] = acc;
    }
    __syncthreads();
    if (j < 21)
        out[(size_t)i * 21 + j] = part[0][j] + part[1][j] + part[2][j] + part[3][j] + fcb[j];
}

// ---------------- host ----------------
extern "C" void kernel_launch(void* const* d_in, const int* in_sizes, int n_in,
                              void* d_out, int out_size)
{
    const float* x_protein = (const float*)d_in[0];
    const float* x_ligand  = (const float*)d_in[1];
    const int*   ei_pp     = (const int*)d_in[2];
    const float* ea_pp     = (const float*)d_in[3];
    const int*   ei_lp     = (const int*)d_in[4];
    const float* ea_lp     = (const float*)d_in[5];
    const int*   ei_pl     = (const int*)d_in[6];
    const float* ea_pl     = (const float*)d_in[7];
    const float* Wp        = (const float*)d_in[8];
    const float* bp        = (const float*)d_in[9];
    const float* Wl        = (const float*)d_in[10];
    const float* bl        = (const float*)d_in[11];
    const float* Wf        = (const float*)d_in[12];
    const float* bf        = (const float*)d_in[13];
    const float* Ws        = (const float*)d_in[14];
    const float* bs        = (const float*)d_in[15];
    const float* bn_w      = (const float*)d_in[16];
    const float* bn_b      = (const float*)d_in[17];
    const float* ln_w      = (const float*)d_in[18];
    const float* ln_b      = (const float*)d_in[19];
    const float* lno_w     = (const float*)d_in[20];
    const float* lno_b     = (const float*)d_in[21];
    const float* fc_w      = (const float*)d_in[22];
    const float* fc_b      = (const float*)d_in[23];
    float* out = (float*)d_out;

    float *xpA, *xpB, *xlA, *xlB, *agg_pp, *agg_lp, *agg_pl, *su;
    __half2 *Th;
    __half *Pp, *Pl, *xph, *xlh, *Wh;
    int *cnt, *offs, *cur, *ssrc, *chs, *chb;
    cudaGetSymbolAddress((void**)&xpA, g_xpA);
    cudaGetSymbolAddress((void**)&xpB, g_xpB);
    cudaGetSymbolAddress((void**)&xlA, g_xlA);
    cudaGetSymbolAddress((void**)&xlB, g_xlB);
    cudaGetSymbolAddress((void**)&xph, g_xph);
    cudaGetSymbolAddress((void**)&xlh, g_xlh);
    cudaGetSymbolAddress((void**)&Wh, g_Wh);
    cudaGetSymbolAddress((void**)&Pp, g_Pp);
    cudaGetSymbolAddress((void**)&Pl, g_Pl);
    cudaGetSymbolAddress((void**)&agg_pp, g_agg_pp);
    cudaGetSymbolAddress((void**)&agg_lp, g_agg_lp);
    cudaGetSymbolAddress((void**)&agg_pl, g_agg_pl);
    cudaGetSymbolAddress((void**)&Th, g_Th);
    cudaGetSymbolAddress((void**)&cnt, g_cnt);
    cudaGetSymbolAddress((void**)&offs, g_off);
    cudaGetSymbolAddress((void**)&cur, g_cur);
    cudaGetSymbolAddress((void**)&ssrc, g_ssrc);
    cudaGetSymbolAddress((void**)&su, g_su);
    cudaGetSymbolAddress((void**)&chs, g_chunksum);
    cudaGetSymbolAddress((void**)&chb, g_chunkbase);

    cudaFuncSetAttribute(proj_mma, cudaFuncAttributeMaxDynamicSharedMemorySize, SMEM_MMA_BYTES);

    embed_kernel<<<NP + NL, 128>>>(x_protein, Wp, bp, x_ligand, Wl, bl, xpA, xlA, xph, xlh);
    wconv<<<dim3(48, 128), 128>>>(Wf, Ws, Wh);
    lut_build<<<dim3(NBIN, 12), 256>>>(Wf, Ws, Th);
    cudaMemsetAsync(cnt, 0, NCNT * sizeof(int), 0);
    hist_all<<<(ETOT + 255) / 256, 256>>>(ei_pp, ei_lp, ei_pl, cnt);
    proj_mma<<<dim3((NP + 127) / 128, 12), 256, SMEM_MMA_BYTES>>>(xph, xlh, Wh, Pp, Pl);
    scanA<<<CHT, 1024>>>(cnt, offs, chs);
    scanB<<<1, 32>>>(chs, chb, offs);
    scanC<<<CHT, 1024>>>(offs, chb, cur);
    scatter_all<<<(ETOT + 255) / 256, 256>>>(ei_pp, ea_pp, ei_lp, ea_lp, ei_pl, ea_pl,
                                             cur, ssrc, su);

    float* xp_cur = xpA; float* xp_nxt = xpB;
    float* xl_cur = xlA; float* xl_nxt = xlB;

    for (int l = 0; l < NLAYER; ++l) {
        if (l > 0)
            proj_mma<<<dim3((NP + 127) / 128, 12), 256, SMEM_MMA_BYTES>>>(
                xph, xlh, Wh + (size_t)l * 12 * 128 * 128, Pp, Pl);

        EdgeArgs ea;
        ea.off[0] = offs;              ea.ssrc[0] = ssrc;             ea.su[0] = su;
        ea.T[0] = Th + (size_t)(l * 3 + 0) * NBIN * 256;
        ea.Pd[0] = Pp + 0 * H; ea.dstr[0] = 8 * H;
        ea.Ps[0] = Pp + 2 * H; ea.sstr[0] = 8 * H;
        ea.bfp[0] = bf + (size_t)(l * 3 + 0) * H; ea.bsp[0] = bs + (size_t)(l * 3 + 0) * H;
        ea.agg[0] = agg_pp;
        ea.off[1] = offs + NP + 1;     ea.ssrc[1] = ssrc + EPP;       ea.su[1] = su + EPP;
        ea.T[1] = Th + (size_t)(l * 3 + 1) * NBIN * 256;
        ea.Pd[1] = Pp + 4 * H; ea.dstr[1] = 8 * H;
        ea.Ps[1] = Pl + 0 * H; ea.sstr[1] = 4 * H;
        ea.bfp[1] = bf + (size_t)(l * 3 + 1) * H; ea.bsp[1] = bs + (size_t)(l * 3 + 1) * H;
        ea.agg[1] = agg_lp;
        ea.off[2] = offs + 2 * NP + 2; ea.ssrc[2] = ssrc + EPP + ELP; ea.su[2] = su + EPP + ELP;
        ea.T[2] = Th + (size_t)(l * 3 + 2) * NBIN * 256;
        ea.Pd[2] = Pl + 2 * H; ea.dstr[2] = 4 * H;
        ea.Ps[2] = Pp + 6 * H; ea.sstr[2] = 8 * H;
        ea.bfp[2] = bf + (size_t)(l * 3 + 2) * H; ea.bsp[2] = bs + (size_t)(l * 3 + 2) * H;
        ea.agg[2] = agg_pl;

        edge_all<<<(2 * NP + NL + 7) / 8, 256>>>(ea);

        node_update<<<(NP + NL + 7) / 8, 256>>>(xp_cur, agg_pp, agg_lp,
                                                xl_cur, agg_pl,
                                                bn_w, bn_b, ln_w, ln_b, l,
                                                xp_nxt, xl_nxt, xph, xlh);

        float* t;
        t = xp_cur; xp_cur = xp_nxt; xp_nxt = t;
        t = xl_cur; xl_cur = xl_nxt; xl_nxt = t;
    }

    final_kernel<<<NP, 128>>>(xp_cur, lno_w, lno_b, fc_w, fc_b, out);
}

// round 14
// speedup vs baseline: 1.1902x; 1.1902x over previous
#include <cuda_runtime.h>
#include <cuda_fp16.h>
#include <cstdint>
#include <cstddef>

#define NP 50000
#define NL 10000
#define H  128
#define D  16
#define NLAYER 4
#define EPP 500000
#define ELP 100000
#define EPL 100000
#define ETOT (EPP + ELP + EPL)
#define NCNT (2 * NP + NL)
#define NBIN 512
#define CH0 49
#define CH1 49
#define CH2 10
#define CHT (CH0 + CH1 + CH2)

// ---------------- scratch (device globals; no runtime allocation) ----------------
__device__ float  g_xpA[NP * H];
__device__ float  g_xpB[NP * H];
__device__ float  g_xlA[NL * H];
__device__ float  g_xlB[NL * H];
__device__ __align__(16) __half g_xph[NP * H];
__device__ __align__(16) __half g_xlh[NL * H];
__device__ __align__(16) __half g_Wh[(size_t)48 * 128 * 128];
__device__ __align__(16) __half g_Pp[(size_t)NP * 8 * H];   // f|s pairs adjacent (+0/+H)
__device__ __align__(16) __half g_Pl[(size_t)NL * 4 * H];
// fp16 interleaved LUT: Th[lt][bin][col] = (T(bin), T(bin+1))
__device__ __align__(16) __half2 g_Th[(size_t)12 * NBIN * 256];
__device__ int    g_cnt[NCNT];
__device__ int    g_off[NCNT + 3];
__device__ int    g_cur[NCNT];
__device__ int    g_ssrc[ETOT];
__device__ float  g_su[ETOT];
__device__ int    g_chunksum[CHT];
__device__ int    g_chunkbase[CHT];

// ---------------- small helpers ----------------
__device__ __forceinline__ uint32_t smem_u32(const void* p) {
    uint32_t a;
    asm("{ .reg .u64 t; cvta.to.shared.u64 t, %1; cvt.u32.u64 %0, t; }" : "=r"(a) : "l"(p));
    return a;
}
__device__ __forceinline__ void ldsm_x4(uint32_t& r0, uint32_t& r1, uint32_t& r2, uint32_t& r3,
                                        uint32_t addr) {
    asm volatile("ldmatrix.sync.aligned.m8n8.x4.shared.b16 {%0,%1,%2,%3}, [%4];"
                 : "=r"(r0), "=r"(r1), "=r"(r2), "=r"(r3) : "r"(addr));
}
__device__ __forceinline__ void block_reduce_2(float& s, float& q, float* shbuf)
{
    unsigned m = 0xffffffffu;
    #pragma unroll
    for (int o = 16; o > 0; o >>= 1) {
        s += __shfl_down_sync(m, s, o);
        q += __shfl_down_sync(m, q, o);
    }
    int lane = threadIdx.x & 31, wid = threadIdx.x >> 5;
    if (lane == 0) { shbuf[wid] = s; shbuf[4 + wid] = q; }
    __syncthreads();
    s = shbuf[0] + shbuf[1] + shbuf[2] + shbuf[3];
    q = shbuf[4] + shbuf[5] + shbuf[6] + shbuf[7];
    __syncthreads();
}
__device__ __forceinline__ float sig_tanh(float x) {
    float t;
    asm("tanh.approx.f32 %0, %1;" : "=f"(t) : "f"(x * 0.5f));
    return 0.5f * t + 0.5f;
}
__device__ __forceinline__ float softplus_f(float x) {
    return fmaxf(x, 0.f) + __logf(1.0f + __expf(-fabsf(x)));
}
__device__ __forceinline__ float4 h4f(uint2 v) {
    __half2 a = *(__half2*)&v.x;
    __half2 b = *(__half2*)&v.y;
    float2 fa = __half22float2(a);
    float2 fb = __half22float2(b);
    return make_float4(fa.x, fa.y, fb.x, fb.y);
}
__device__ __forceinline__ float4 cg_ln_relu(float4 a, float4 lw, float4 lb)
{
    float s = a.x + a.y + a.z + a.w;
    float q = a.x * a.x + a.y * a.y + a.z * a.z + a.w * a.w;
    #pragma unroll
    for (int o = 16; o > 0; o >>= 1) {
        s += __shfl_xor_sync(0xffffffffu, s, o);
        q += __shfl_xor_sync(0xffffffffu, q, o);
    }
    float mean = s * (1.0f / H);
    float var = q * (1.0f / H) - mean * mean;
    float r = rsqrtf(var + 1e-5f);
    float4 y;
    y.x = fmaxf((a.x - mean) * r * lw.x + lb.x, 0.f);
    y.y = fmaxf((a.y - mean) * r * lw.y + lb.y, 0.f);
    y.z = fmaxf((a.z - mean) * r * lw.z + lb.z, 0.f);
    y.w = fmaxf((a.w - mean) * r * lw.w + lb.w, 0.f);
    return y;
}

// ---------------- CSR build ----------------
__global__ void hist_all(const int* __restrict__ ei_pp, const int* __restrict__ ei_lp,
                         const int* __restrict__ ei_pl, int* __restrict__ cnt)
{
    int idx = blockIdx.x * blockDim.x + threadIdx.x;
    if (idx >= ETOT) return;
    if (idx < EPP) {
        atomicAdd(&cnt[ei_pp[EPP + idx]], 1);
    } else if (idx < EPP + ELP) {
        int e = idx - EPP;
        atomicAdd(&cnt[NP + ei_lp[ELP + e]], 1);
    } else {
        int e = idx - EPP - ELP;
        atomicAdd(&cnt[2 * NP + ei_pl[EPL + e]], 1);
    }
}

__global__ __launch_bounds__(1024) void scanA(const int* __restrict__ cnt,
                                              int* __restrict__ off,
                                              int* __restrict__ chunksum)
{
    __shared__ int s[1024];
    int bid = blockIdx.x;
    const int* cbase; int* obase; int N; int c;
    if (bid < CH0)            { cbase = cnt;          obase = off;              N = NP; c = bid; }
    else if (bid < CH0 + CH1) { cbase = cnt + NP;     obase = off + NP + 1;     N = NP; c = bid - CH0; }
    else                      { cbase = cnt + 2 * NP; obase = off + 2 * NP + 2; N = NL; c = bid - CH0 - CH1; }
    int tid = threadIdx.x;
    int i = c * 1024 + tid;
    int v = (i < N) ? cbase[i] : 0;
    s[tid] = v;
    __syncthreads();
    #pragma unroll
    for (int o = 1; o < 1024; o <<= 1) {
        int t = (tid >= o) ? s[tid - o] : 0;
        __syncthreads();
        s[tid] += t;
        __syncthreads();
    }
    if (i < N) obase[i] = s[tid] - v;
    if (tid == 1023) chunksum[bid] = s[1023];
}

__global__ void scanB(const int* __restrict__ chunksum, int* __restrict__ chunkbase,
                      int* __restrict__ off)
{
    int t = threadIdx.x;
    if (t == 0) {
        int b = 0;
        for (int c = 0; c < CH0; ++c) { chunkbase[c] = b; b += chunksum[c]; }
        off[NP] = b;
    } else if (t == 1) {
        int b = 0;
        for (int c = 0; c < CH1; ++c) { chunkbase[CH0 + c] = b; b += chunksum[CH0 + c]; }
        off[NP + 1 + NP] = b;
    } else if (t == 2) {
        int b = 0;
        for (int c = 0; c < CH2; ++c) { chunkbase[CH0 + CH1 + c] = b; b += chunksum[CH0 + CH1 + c]; }
        off[2 * NP + 2 + NL] = b;
    }
}

__global__ __launch_bounds__(1024) void scanC(int* __restrict__ off,
                                              const int* __restrict__ chunkbase,
                                              int* __restrict__ cur)
{
    int bid = blockIdx.x;
    int* obase; int* curb; int N; int c;
    if (bid < CH0)            { obase = off;              curb = cur;          N = NP; c = bid; }
    else if (bid < CH0 + CH1) { obase = off + NP + 1;     curb = cur + NP;     N = NP; c = bid - CH0; }
    else                      { obase = off + 2 * NP + 2; curb = cur + 2 * NP; N = NL; c = bid - CH0 - CH1; }
    int i = c * 1024 + threadIdx.x;
    if (i < N) {
        int v = obase[i] + chunkbase[bid];
        obase[i] = v;
        curb[i] = v;
    }
}

__global__ void scatter_all(const int* __restrict__ ei_pp, const float* __restrict__ ea_pp,
                            const int* __restrict__ ei_lp, const float* __restrict__ ea_lp,
                            const int* __restrict__ ei_pl, const float* __restrict__ ea_pl,
                            int* __restrict__ cur, int* __restrict__ ssrc,
                            float* __restrict__ su)
{
    const float usc = (float)NBIN / 8.0f;
    int idx = blockIdx.x * blockDim.x + threadIdx.x;
    if (idx >= ETOT) return;
    if (idx < EPP) {
        int e = idx;
        int d = ei_pp[EPP + e];
        int p = atomicAdd(&cur[d], 1);
        ssrc[p] = ei_pp[e];
        su[p] = ea_pp[e] * usc;
    } else if (idx < EPP + ELP) {
        int e = idx - EPP;
        int d = ei_lp[ELP + e];
        int p = EPP + atomicAdd(&cur[NP + d], 1);
        ssrc[p] = ei_lp[e];
        su[p] = ea_lp[e] * usc;
    } else {
        int e = idx - EPP - ELP;
        int d = ei_pl[EPL + e];
        int p = EPP + ELP + atomicAdd(&cur[2 * NP + d], 1);
        ssrc[p] = ei_pl[e];
        su[p] = ea_pl[e] * usc;
    }
}

// ---------------- LUT build: fp16 interleaved (lo, hi) ----------------
__global__ __launch_bounds__(256) void lut_build(
    const float* __restrict__ Wf, const float* __restrict__ Ws, __half2* __restrict__ Th)
{
    int b = blockIdx.x;
    int lt = blockIdx.y;
    int j = threadIdx.x;
    const float step = 8.0f / 15.0f;
    const float coeff = -0.5f / (step * step);
    const float* W = (j < 128 ? Wf : Ws) + ((size_t)lt * 272 + 256) * H + (j & 127);
    float accL = 0.f, accH = 0.f;
    float dL = (float)b * (8.0f / (float)NBIN);
    float dH = (float)(b + 1) * (8.0f / (float)NBIN);
    #pragma unroll
    for (int k = 0; k < 16; ++k) {
        float w = W[(size_t)k * H];
        float dltL = dL - (float)k * step;
        float dltH = dH - (float)k * step;
        accL += __expf(coeff * dltL * dltL) * w;
        accH += __expf(coeff * dltH * dltH) * w;
    }
    Th[((size_t)lt * NBIN + b) * 256 + j] = __floats2half2_rn(accL, accH);
}

// ---------------- fp16 weight pre-convert ----------------
__global__ __launch_bounds__(128) void wconv(
    const float* __restrict__ Wf, const float* __restrict__ Ws, __half* __restrict__ Wh)
{
    const int bmap[12] = {0, 0, 0, 0, 1, 1, 2, 2, 1, 1, 2, 2};
    const int rmap[12] = {0, 0, 128, 128, 0, 0, 128, 128, 128, 128, 0, 0};
    const int fmap[12] = {1, 0, 1, 0, 1, 0, 1, 0, 1, 0, 1, 0};
    int ls = blockIdx.x;
    int layer = ls / 12, s = ls % 12;
    int k = blockIdx.y;
    int n = threadIdx.x;
    const float* base = fmap[s] ? Wf : Ws;
    float v = base[((size_t)(layer * 3 + bmap[s]) * 272 + rmap[s] + k) * H + n];
    Wh[((size_t)ls * 128 + n) * 128 + k] = __float2half(v);
}

// ---------------- merged initial embedding ----------------
__global__ __launch_bounds__(128) void embed_kernel(
    const float* __restrict__ xp, const float* __restrict__ Wp, const float* __restrict__ bp,
    const float* __restrict__ xl, const float* __restrict__ Wl, const float* __restrict__ bl,
    float* __restrict__ outp, float* __restrict__ outl,
    __half* __restrict__ outph, __half* __restrict__ outlh)
{
    int i = blockIdx.x;
    int j = threadIdx.x;
    const float *x, *W, *b; float* o; __half* oh; int r;
    if (i < NP) { x = xp; W = Wp; b = bp; o = outp; oh = outph; r = i; }
    else        { x = xl; W = Wl; b = bl; o = outl; oh = outlh; r = i - NP; }
    const float* xr = x + (size_t)r * 6;
    float acc = b[j];
    #pragma unroll
    for (int k = 0; k < 6; ++k) acc += xr[k] * W[k * H + j];
    o[(size_t)r * H + j] = acc;
    oh[(size_t)r * H + j] = __float2half(acc);
}

// ---------------- pipelined fp16 mma GEMM with ldmatrix ----------------
#define APH 72
#define ASTH (128 * APH)
#define BSTH (128 * APH)
#define STGH (ASTH + BSTH)
#define SMEM_MMA_BYTES (2 * STGH * 2)

__global__ __launch_bounds__(256, 2) void proj_mma(
    const __half* __restrict__ Xph, const __half* __restrict__ Xlh,
    const __half* __restrict__ Wh,
    __half* __restrict__ outP, __half* __restrict__ outL)
{
    int slice = blockIdx.y;
    const __half* Xh; __half* out; int N, outStride, col;
    if (slice < 8) { Xh = Xph; out = outP; N = NP; outStride = 8 * H; col = slice; }
    else           { Xh = Xlh; out = outL; N = NL; outStride = 4 * H; col = slice - 8; }
    int m0 = blockIdx.x * 128;
    if (m0 >= N) return;

    extern __shared__ __half smh[];
    uint32_t smb = smem_u32(smh);
    const __half* Whs = Wh + (size_t)slice * 128 * 128;
    int tid = threadIdx.x;
    int lane = tid & 31, warp = tid >> 5;
    int g = lane >> 2, t = lane & 3;

    auto load_stage = [&](int chunk, int s) {
        int kb = chunk * 64;
        uint32_t abase = smb + (uint32_t)(s * STGH) * 2u;
        uint32_t bbase = abase + (uint32_t)ASTH * 2u;
        #pragma unroll
        for (int i = 0; i < 4; ++i) {
            int idx = tid + i * 256;
            int r = idx >> 3, c8 = (idx & 7) * 8;
            uint32_t dst = abase + (uint32_t)(r * APH + c8) * 2u;
            const __half* src = Xh + (size_t)(m0 + r) * H + kb + c8;
            int sz = (m0 + r < N) ? 16 : 0;
            asm volatile("cp.async.cg.shared.global [%0], [%1], 16, %2;"
                         :: "r"(dst), "l"(src), "r"(sz));
        }
        #pragma unroll
        for (int i = 0; i < 4; ++i) {
            int idx = tid + i * 256;
            int n = idx >> 3, k8 = (idx & 7) * 8;
            uint32_t dst = bbase + (uint32_t)(n * APH + k8) * 2u;
            const __half* src = Whs + (size_t)n * 128 + kb + k8;
            asm volatile("cp.async.cg.shared.global [%0], [%1], 16;"
                         :: "r"(dst), "l"(src));
        }
        asm volatile("cp.async.commit_group;" ::: "memory");
    };

    load_stage(0, 0);
    load_stage(1, 1);

    int wm = warp >> 2;
    int wn = warp & 3;
    int mbase = wm * 64;
    int nbase = wn * 32;

    int a_row = lane & 15;
    int a_kh = (lane >> 4) * 8;
    int b_nrow = (lane >> 4) * 8 + (lane & 7);
    int b_kh = ((lane >> 3) & 1) * 8;

    float d[4][4][4];
    #pragma unroll
    for (int i = 0; i < 4; ++i)
        #pragma unroll
        for (int j = 0; j < 4; ++j)
            #pragma unroll
            for (int q = 0; q < 4; ++q) d[i][j][q] = 0.f;

    #pragma unroll
    for (int c = 0; c < 2; ++c) {
        if (c == 0) asm volatile("cp.async.wait_group 1;" ::: "memory");
        else        asm volatile("cp.async.wait_group 0;" ::: "memory");
        __syncthreads();

        uint32_t abase = smb + (uint32_t)(c * STGH) * 2u;
        uint32_t bbase = abase + (uint32_t)ASTH * 2u;

        #pragma unroll
        for (int ks = 0; ks < 4; ++ks) {
            int kbl = ks * 16;
            uint32_t a[4][4];
            #pragma unroll
            for (int i = 0; i < 4; ++i) {
                uint32_t addr = abase +
                    (uint32_t)((mbase + i * 16 + a_row) * APH + kbl + a_kh) * 2u;
                ldsm_x4(a[i][0], a[i][1], a[i][2], a[i][3], addr);
            }
            uint32_t b[4][2];
            #pragma unroll
            for (int jp = 0; jp < 2; ++jp) {
                uint32_t addr = bbase +
                    (uint32_t)((nbase + jp * 16 + b_nrow) * APH + kbl + b_kh) * 2u;
                ldsm_x4(b[2 * jp][0], b[2 * jp][1], b[2 * jp + 1][0], b[2 * jp + 1][1], addr);
            }
            #pragma unroll
            for (int i = 0; i < 4; ++i)
                #pragma unroll
                for (int j = 0; j < 4; ++j) {
                    asm volatile(
                        "mma.sync.aligned.m16n8k16.row.col.f32.f16.f16.f32 "
                        "{%0,%1,%2,%3}, {%4,%5,%6,%7}, {%8,%9}, {%0,%1,%2,%3};"
                        : "+f"(d[i][j][0]), "+f"(d[i][j][1]), "+f"(d[i][j][2]), "+f"(d[i][j][3])
                        : "r"(a[i][0]), "r"(a[i][1]), "r"(a[i][2]), "r"(a[i][3]),
                          "r"(b[j][0]), "r"(b[j][1]));
                }
        }
    }

    size_t colbase = (size_t)col * H;
    #pragma unroll
    for (int i = 0; i < 4; ++i) {
        int gr0 = m0 + mbase + i * 16 + g;
        int gr1 = gr0 + 8;
        #pragma unroll
        for (int j = 0; j < 4; ++j) {
            int gc = nbase + j * 8 + t * 2;
            if (gr0 < N)
                *(__half2*)(out + (size_t)gr0 * outStride + colbase + gc) =
                    __floats2half2_rn(d[i][j][0], d[i][j][1]);
            if (gr1 < N)
                *(__half2*)(out + (size_t)gr1 * outStride + colbase + gc) =
                    __floats2half2_rn(d[i][j][2], d[i][j][3]);
        }
    }
}

// ---------------- fused edge + node-update kernel: warp per node ----------------
struct FusedArgs {
    const int*    off[3];
    const int*    ssrc[3];
    const float*  su[3];
    const __half2* T[3];
    const __half* Pd[3]; int dstr[3];
    const __half* Ps[3]; int sstr[3];
    const float*  bfp[3];
    const float*  bsp[3];
    const float*  bn_w; const float* bn_b;
    const float*  ln_w; const float* ln_b;
    int layer;
    const float*  xp_in; const float* xl_in;
    float* xp_out; float* xl_out;
    __half* xph_out; __half* xlh_out;
};

__device__ __forceinline__ void edge_math(
    float4 fsv, float4 ssv, float u, const __half2* __restrict__ T, int j0,
    float fd0, float fd1, float fd2, float fd3,
    float sd0, float sd1, float sd2, float sd3,
    float& a0, float& a1, float& a2, float& a3, bool valid)
{
    int b = min((int)u, NBIN - 1);
    float w = u - (float)b;
    const __half2* Tb = T + (size_t)b * 256 + j0;
    uint4 fv = *(const uint4*)(Tb);
    uint4 sv = *(const uint4*)(Tb + 128);
    float2 f0p = __half22float2(*(__half2*)&fv.x);
    float2 f1p = __half22float2(*(__half2*)&fv.y);
    float2 f2p = __half22float2(*(__half2*)&fv.z);
    float2 f3p = __half22float2(*(__half2*)&fv.w);
    float2 s0p = __half22float2(*(__half2*)&sv.x);
    float2 s1p = __half22float2(*(__half2*)&sv.y);
    float2 s2p = __half22float2(*(__half2*)&sv.z);
    float2 s3p = __half22float2(*(__half2*)&sv.w);

    float f0 = fd0 + fsv.x + f0p.x + w * (f0p.y - f0p.x);
    float f1 = fd1 + fsv.y + f1p.x + w * (f1p.y - f1p.x);
    float f2 = fd2 + fsv.z + f2p.x + w * (f2p.y - f2p.x);
    float f3 = fd3 + fsv.w + f3p.x + w * (f3p.y - f3p.x);
    float s0 = sd0 + ssv.x + s0p.x + w * (s0p.y - s0p.x);
    float s1 = sd1 + ssv.y + s1p.x + w * (s1p.y - s1p.x);
    float s2 = sd2 + ssv.z + s2p.x + w * (s2p.y - s2p.x);
    float s3 = sd3 + ssv.w + s3p.x + w * (s3p.y - s3p.x);

    if (valid) {
        a0 += sig_tanh(f0) * softplus_f(s0);
        a1 += sig_tanh(f1) * softplus_f(s1);
        a2 += sig_tanh(f2) * softplus_f(s2);
        a3 += sig_tanh(f3) * softplus_f(s3);
    }
}

// accumulate messages for node n over one edge type; returns float4 of agg
__device__ __forceinline__ float4 edge_accum(
    const FusedArgs& fa, int t, int n, int j0)
{
    const int* off = fa.off[t];
    int p0 = off[n], p1 = off[n + 1];

    float4 bf4 = *(const float4*)(fa.bfp[t] + j0);
    float4 bs4 = *(const float4*)(fa.bsp[t] + j0);
    const __half* pd = fa.Pd[t] + (size_t)n * fa.dstr[t] + j0;
    float4 fdv = h4f(*(const uint2*)(pd));
    float4 sdv = h4f(*(const uint2*)(pd + H));
    float fd0 = fdv.x + bf4.x, fd1 = fdv.y + bf4.y, fd2 = fdv.z + bf4.z, fd3 = fdv.w + bf4.w;
    float sd0 = sdv.x + bs4.x, sd1 = sdv.y + bs4.y, sd2 = sdv.z + bs4.z, sd3 = sdv.w + bs4.w;

    const __half* Ps = fa.Ps[t];
    int sstr = fa.sstr[t];
    const int* ssrc = fa.ssrc[t];
    const float* su = fa.su[t];
    const __half2* T = fa.T[t];

    float a0 = 0.f, a1 = 0.f, a2 = 0.f, a3 = 0.f;

    for (int p = p0; p < p1; p += 4) {
        int pe = p1 - 1;
        int i1 = min(p + 1, pe), i2 = min(p + 2, pe), i3 = min(p + 3, pe);
        int sA = ssrc[p], sB = ssrc[i1], sC = ssrc[i2], sD = ssrc[i3];
        float uA = su[p], uB = su[i1], uC = su[i2], uD = su[i3];

        const __half* qA = Ps + (size_t)sA * sstr + j0;
        const __half* qB = Ps + (size_t)sB * sstr + j0;
        const __half* qC = Ps + (size_t)sC * sstr + j0;
        const __half* qD = Ps + (size_t)sD * sstr + j0;
        uint2 rfA = *(const uint2*)(qA);
        uint2 rfB = *(const uint2*)(qB);
        uint2 rfC = *(const uint2*)(qC);
        uint2 rfD = *(const uint2*)(qD);
        uint2 rsA = *(const uint2*)(qA + H);
        uint2 rsB = *(const uint2*)(qB + H);
        uint2 rsC = *(const uint2*)(qC + H);
        uint2 rsD = *(const uint2*)(qD + H);

        edge_math(h4f(rfA), h4f(rsA), uA, T, j0, fd0, fd1, fd2, fd3, sd0, sd1, sd2, sd3,
                  a0, a1, a2, a3, true);
        edge_math(h4f(rfB), h4f(rsB), uB, T, j0, fd0, fd1, fd2, fd3, sd0, sd1, sd2, sd3,
                  a0, a1, a2, a3, p + 1 < p1);
        edge_math(h4f(rfC), h4f(rsC), uC, T, j0, fd0, fd1, fd2, fd3, sd0, sd1, sd2, sd3,
                  a0, a1, a2, a3, p + 2 < p1);
        edge_math(h4f(rfD), h4f(rsD), uD, T, j0, fd0, fd1, fd2, fd3, sd0, sd1, sd2, sd3,
                  a0, a1, a2, a3, p + 3 < p1);
    }
    return make_float4(a0, a1, a2, a3);
}

__device__ __forceinline__ float4 bn_res(float4 g, float4 x, const float* bnw,
                                         const float* bnb, int j0)
{
    const float bnf = rsqrtf(1.0f + 1e-5f);
    float4 bw = *(const float4*)(bnw + j0);
    float4 bb = *(const float4*)(bnb + j0);
    float4 a;
    a.x = g.x * (bw.x * bnf) + bb.x + x.x;
    a.y = g.y * (bw.y * bnf) + bb.y + x.y;
    a.z = g.z * (bw.z * bnf) + bb.z + x.z;
    a.w = g.w * (bw.w * bnf) + bb.w + x.w;
    return a;
}

__global__ __launch_bounds__(256) void edge_update(FusedArgs fa)
{
    int w = blockIdx.x * 8 + (threadIdx.x >> 5);
    int lane = threadIdx.x & 31;
    int j0 = lane * 4;
    int l = fa.layer;

    if (w < NP) {
        int n = w;
        float4 g1 = edge_accum(fa, 0, n, j0);   // pp
        float4 g2 = edge_accum(fa, 1, n, j0);   // lp

        size_t off = (size_t)n * H + j0;
        float4 x = *(const float4*)(fa.xp_in + off);

        size_t pb0 = (size_t)(l * 3 + 0) * H;
        float4 a1 = bn_res(g1, x, fa.bn_w + pb0, fa.bn_b + pb0, j0);
        float4 y1 = cg_ln_relu(a1, *(const float4*)(fa.ln_w + pb0 + j0),
                               *(const float4*)(fa.ln_b + pb0 + j0));
        size_t pb1 = (size_t)(l * 3 + 1) * H;
        float4 a2 = bn_res(g2, x, fa.bn_w + pb1, fa.bn_b + pb1, j0);
        float4 y2 = cg_ln_relu(a2, *(const float4*)(fa.ln_w + pb1 + j0),
                               *(const float4*)(fa.ln_b + pb1 + j0));
        float4 r;
        r.x = y1.x + y2.x + 2.f * x.x;
        r.y = y1.y + y2.y + 2.f * x.y;
        r.z = y1.z + y2.z + 2.f * x.z;
        r.w = y1.w + y2.w + 2.f * x.w;
        *(float4*)(fa.xp_out + off) = r;
        *(__half2*)(fa.xph_out + off) = __floats2half2_rn(r.x, r.y);
        *(__half2*)(fa.xph_out + off + 2) = __floats2half2_rn(r.z, r.w);
    } else if (w < NP + NL) {
        int n = w - NP;
        float4 g = edge_accum(fa, 2, n, j0);    // pl

        size_t off = (size_t)n * H + j0;
        float4 x = *(const float4*)(fa.xl_in + off);
        size_t pb2 = (size_t)(l * 3 + 2) * H;
        float4 a = bn_res(g, x, fa.bn_w + pb2, fa.bn_b + pb2, j0);
        float4 y = cg_ln_relu(a, *(const float4*)(fa.ln_w + pb2 + j0),
                              *(const float4*)(fa.ln_b + pb2 + j0));
        float4 r;
        r.x = y.x + x.x; r.y = y.y + x.y; r.z = y.z + x.z; r.w = y.w + x.w;
        *(float4*)(fa.xl_out + off) = r;
        *(__half2*)(fa.xlh_out + off) = __floats2half2_rn(r.x, r.y);
        *(__half2*)(fa.xlh_out + off + 2) = __floats2half2_rn(r.z, r.w);
    }
}

// ---------------- final: LN(xp) @ fc_w + fc_b ----------------
__global__ __launch_bounds__(128) void final_kernel(
    const float* __restrict__ xp,
    const float* __restrict__ lnw, const float* __restrict__ lnb,
    const float* __restrict__ fcw, const float* __restrict__ fcb,
    float* __restrict__ out)
{
    __shared__ float sh[8];
    __shared__ float yb[H];
    __shared__ float part[4][21];
    int i = blockIdx.x, j = threadIdx.x;
    float x = xp[(size_t)i * H + j];
    float s = x, q = x * x;
    block_reduce_2(s, q, sh);
    float mean = s * (1.0f / H);
    float var = q * (1.0f / H) - mean * mean;
    yb[j] = (x - mean) * rsqrtf(var + 1e-5f) * lnw[j] + lnb[j];
    __syncthreads();
    if (j < 84) {
        int c = j % 21, qq = j / 21;
        float acc = 0.f;
        #pragma unroll
        for (int t = 0; t < 32; ++t) acc += yb[qq * 32 + t] * fcw[(qq * 32 + t) * 21 + c];
        part[qq][c] = acc;
    }
    __syncthreads();
    if (j < 21)
        out[(size_t)i * 21 + j] = part[0][j] + part[1][j] + part[2][j] + part[3][j] + fcb[j];
}

// ---------------- host ----------------
extern "C" void kernel_launch(void* const* d_in, const int* in_sizes, int n_in,
                              void* d_out, int out_size)
{
    const float* x_protein = (const float*)d_in[0];
    const float* x_ligand  = (const float*)d_in[1];
    const int*   ei_pp     = (const int*)d_in[2];
    const float* ea_pp     = (const float*)d_in[3];
    const int*   ei_lp     = (const int*)d_in[4];
    const float* ea_lp     = (const float*)d_in[5];
    const int*   ei_pl     = (const int*)d_in[6];
    const float* ea_pl     = (const float*)d_in[7];
    const float* Wp        = (const float*)d_in[8];
    const float* bp        = (const float*)d_in[9];
    const float* Wl        = (const float*)d_in[10];
    const float* bl        = (const float*)d_in[11];
    const float* Wf        = (const float*)d_in[12];
    const float* bf        = (const float*)d_in[13];
    const float* Ws        = (const float*)d_in[14];
    const float* bs        = (const float*)d_in[15];
    const float* bn_w      = (const float*)d_in[16];
    const float* bn_b      = (const float*)d_in[17];
    const float* ln_w      = (const float*)d_in[18];
    const float* ln_b      = (const float*)d_in[19];
    const float* lno_w     = (const float*)d_in[20];
    const float* lno_b     = (const float*)d_in[21];
    const float* fc_w      = (const float*)d_in[22];
    const float* fc_b      = (const float*)d_in[23];
    float* out = (float*)d_out;

    float *xpA, *xpB, *xlA, *xlB, *su;
    __half2 *Th;
    __half *Pp, *Pl, *xph, *xlh, *Wh;
    int *cnt, *offs, *cur, *ssrc, *chs, *chb;
    cudaGetSymbolAddress((void**)&xpA, g_xpA);
    cudaGetSymbolAddress((void**)&xpB, g_xpB);
    cudaGetSymbolAddress((void**)&xlA, g_xlA);
    cudaGetSymbolAddress((void**)&xlB, g_xlB);
    cudaGetSymbolAddress((void**)&xph, g_xph);
    cudaGetSymbolAddress((void**)&xlh, g_xlh);
    cudaGetSymbolAddress((void**)&Wh, g_Wh);
    cudaGetSymbolAddress((void**)&Pp, g_Pp);
    cudaGetSymbolAddress((void**)&Pl, g_Pl);
    cudaGetSymbolAddress((void**)&Th, g_Th);
    cudaGetSymbolAddress((void**)&cnt, g_cnt);
    cudaGetSymbolAddress((void**)&offs, g_off);
    cudaGetSymbolAddress((void**)&cur, g_cur);
    cudaGetSymbolAddress((void**)&ssrc, g_ssrc);
    cudaGetSymbolAddress((void**)&su, g_su);
    cudaGetSymbolAddress((void**)&chs, g_chunksum);
    cudaGetSymbolAddress((void**)&chb, g_chunkbase);

    cudaFuncSetAttribute(proj_mma, cudaFuncAttributeMaxDynamicSharedMemorySize, SMEM_MMA_BYTES);

    embed_kernel<<<NP + NL, 128>>>(x_protein, Wp, bp, x_ligand, Wl, bl, xpA, xlA, xph, xlh);
    wconv<<<dim3(48, 128), 128>>>(Wf, Ws, Wh);
    lut_build<<<dim3(NBIN, 12), 256>>>(Wf, Ws, Th);
    cudaMemsetAsync(cnt, 0, NCNT * sizeof(int), 0);
    hist_all<<<(ETOT + 255) / 256, 256>>>(ei_pp, ei_lp, ei_pl, cnt);
    proj_mma<<<dim3((NP + 127) / 128, 12), 256, SMEM_MMA_BYTES>>>(xph, xlh, Wh, Pp, Pl);
    scanA<<<CHT, 1024>>>(cnt, offs, chs);
    scanB<<<1, 32>>>(chs, chb, offs);
    scanC<<<CHT, 1024>>>(offs, chb, cur);
    scatter_all<<<(ETOT + 255) / 256, 256>>>(ei_pp, ea_pp, ei_lp, ea_lp, ei_pl, ea_pl,
                                             cur, ssrc, su);

    float* xp_cur = xpA; float* xp_nxt = xpB;
    float* xl_cur = xlA; float* xl_nxt = xlB;

    for (int l = 0; l < NLAYER; ++l) {
        if (l > 0)
            proj_mma<<<dim3((NP + 127) / 128, 12), 256, SMEM_MMA_BYTES>>>(
                xph, xlh, Wh + (size_t)l * 12 * 128 * 128, Pp, Pl);

        FusedArgs fa;
        fa.off[0] = offs;              fa.ssrc[0] = ssrc;             fa.su[0] = su;
        fa.T[0] = Th + (size_t)(l * 3 + 0) * NBIN * 256;
        fa.Pd[0] = Pp + 0 * H; fa.dstr[0] = 8 * H;
        fa.Ps[0] = Pp + 2 * H; fa.sstr[0] = 8 * H;
        fa.bfp[0] = bf + (size_t)(l * 3 + 0) * H; fa.bsp[0] = bs + (size_t)(l * 3 + 0) * H;
        fa.off[1] = offs + NP + 1;     fa.ssrc[1] = ssrc + EPP;       fa.su[1] = su + EPP;
        fa.T[1] = Th + (size_t)(l * 3 + 1) * NBIN * 256;
        fa.Pd[1] = Pp + 4 * H; fa.dstr[1] = 8 * H;
        fa.Ps[1] = Pl + 0 * H; fa.sstr[1] = 4 * H;
        fa.bfp[1] = bf + (size_t)(l * 3 + 1) * H; fa.bsp[1] = bs + (size_t)(l * 3 + 1) * H;
        fa.off[2] = offs + 2 * NP + 2; fa.ssrc[2] = ssrc + EPP + ELP; fa.su[2] = su + EPP + ELP;
        fa.T[2] = Th + (size_t)(l * 3 + 2) * NBIN * 256;
        fa.Pd[2] = Pl + 2 * H; fa.dstr[2] = 4 * H;
        fa.Ps[2] = Pp + 6 * H; fa.sstr[2] = 8 * H;
        fa.bfp[2] = bf + (size_t)(l * 3 + 2) * H; fa.bsp[2] = bs + (size_t)(l * 3 + 2) * H;
        fa.bn_w = bn_w; fa.bn_b = bn_b; fa.ln_w = ln_w; fa.ln_b = ln_b;
        fa.layer = l;
        fa.xp_in = xp_cur; fa.xl_in = xl_cur;
        fa.xp_out = xp_nxt; fa.xl_out = xl_nxt;
        fa.xph_out = xph; fa.xlh_out = xlh;

        edge_update<<<(NP + NL + 7) / 8, 256>>>(fa);

        float* t;
        t = xp_cur; xp_cur = xp_nxt; xp_nxt = t;
        t = xl_cur; xl_cur = xl_nxt; xl_nxt = t;
    }

    final_kernel<<<NP, 128>>>(xp_cur, lno_w, lno_b, fc_w, fc_b, out);
}

// round 15
// speedup vs baseline: 1.2073x; 1.0144x over previous
#include <cuda_runtime.h>
#include <cuda_fp16.h>
#include <cstdint>
#include <cstddef>

#define NP 50000
#define NL 10000
#define H  128
#define D  16
#define NLAYER 4
#define EPP 500000
#define ELP 100000
#define EPL 100000
#define ETOT (EPP + ELP + EPL)
#define NCNT (2 * NP + NL)
#define NBIN 512
#define CH0 49
#define CH1 49
#define CH2 10
#define CHT (CH0 + CH1 + CH2)

// ---------------- scratch (device globals; no runtime allocation) ----------------
__device__ float  g_xpA[NP * H];
__device__ float  g_xpB[NP * H];
__device__ float  g_xlA[NL * H];
__device__ float  g_xlB[NL * H];
__device__ __align__(16) __half g_xph[NP * H];
__device__ __align__(16) __half g_xlh[NL * H];
__device__ __align__(16) __half g_Wh[(size_t)48 * 128 * 128];
__device__ __align__(16) __half g_Pp[(size_t)NP * 8 * H];   // f|s pairs adjacent (+0/+H)
__device__ __align__(16) __half g_Pl[(size_t)NL * 4 * H];
// fp16 interleaved LUT: Th[lt][bin][col] = (T(bin), T(bin+1))
__device__ __align__(16) __half2 g_Th[(size_t)12 * NBIN * 256];
__device__ int    g_cnt[NCNT];
__device__ int    g_off[NCNT + 3];
__device__ int    g_cur[NCNT];
__device__ int    g_ssrc[ETOT];
__device__ float  g_su[ETOT];
__device__ int    g_chunksum[CHT];
__device__ int    g_chunkbase[CHT];

// ---------------- small helpers ----------------
__device__ __forceinline__ uint32_t smem_u32(const void* p) {
    uint32_t a;
    asm("{ .reg .u64 t; cvta.to.shared.u64 t, %1; cvt.u32.u64 %0, t; }" : "=r"(a) : "l"(p));
    return a;
}
__device__ __forceinline__ void ldsm_x4(uint32_t& r0, uint32_t& r1, uint32_t& r2, uint32_t& r3,
                                        uint32_t addr) {
    asm volatile("ldmatrix.sync.aligned.m8n8.x4.shared.b16 {%0,%1,%2,%3}, [%4];"
                 : "=r"(r0), "=r"(r1), "=r"(r2), "=r"(r3) : "r"(addr));
}
__device__ __forceinline__ float sig_tanh(float x) {
    float t;
    asm("tanh.approx.f32 %0, %1;" : "=f"(t) : "f"(x * 0.5f));
    return 0.5f * t + 0.5f;
}
__device__ __forceinline__ float softplus_f(float x) {
    return fmaxf(x, 0.f) + __logf(1.0f + __expf(-fabsf(x)));
}
__device__ __forceinline__ float4 h4f(uint2 v) {
    __half2 a = *(__half2*)&v.x;
    __half2 b = *(__half2*)&v.y;
    float2 fa = __half22float2(a);
    float2 fb = __half22float2(b);
    return make_float4(fa.x, fa.y, fb.x, fb.y);
}
__device__ __forceinline__ float4 cg_ln_relu(float4 a, float4 lw, float4 lb)
{
    float s = a.x + a.y + a.z + a.w;
    float q = a.x * a.x + a.y * a.y + a.z * a.z + a.w * a.w;
    #pragma unroll
    for (int o = 16; o > 0; o >>= 1) {
        s += __shfl_xor_sync(0xffffffffu, s, o);
        q += __shfl_xor_sync(0xffffffffu, q, o);
    }
    float mean = s * (1.0f / H);
    float var = q * (1.0f / H) - mean * mean;
    float r = rsqrtf(var + 1e-5f);
    float4 y;
    y.x = fmaxf((a.x - mean) * r * lw.x + lb.x, 0.f);
    y.y = fmaxf((a.y - mean) * r * lw.y + lb.y, 0.f);
    y.z = fmaxf((a.z - mean) * r * lw.z + lb.z, 0.f);
    y.w = fmaxf((a.w - mean) * r * lw.w + lb.w, 0.f);
    return y;
}

// ---------------- CSR build ----------------
__global__ void hist_all(const int* __restrict__ ei_pp, const int* __restrict__ ei_lp,
                         const int* __restrict__ ei_pl, int* __restrict__ cnt)
{
    int idx = blockIdx.x * blockDim.x + threadIdx.x;
    if (idx >= ETOT) return;
    if (idx < EPP) {
        atomicAdd(&cnt[ei_pp[EPP + idx]], 1);
    } else if (idx < EPP + ELP) {
        int e = idx - EPP;
        atomicAdd(&cnt[NP + ei_lp[ELP + e]], 1);
    } else {
        int e = idx - EPP - ELP;
        atomicAdd(&cnt[2 * NP + ei_pl[EPL + e]], 1);
    }
}

__global__ __launch_bounds__(1024) void scanA(const int* __restrict__ cnt,
                                              int* __restrict__ off,
                                              int* __restrict__ chunksum)
{
    __shared__ int s[1024];
    int bid = blockIdx.x;
    const int* cbase; int* obase; int N; int c;
    if (bid < CH0)            { cbase = cnt;          obase = off;              N = NP; c = bid; }
    else if (bid < CH0 + CH1) { cbase = cnt + NP;     obase = off + NP + 1;     N = NP; c = bid - CH0; }
    else                      { cbase = cnt + 2 * NP; obase = off + 2 * NP + 2; N = NL; c = bid - CH0 - CH1; }
    int tid = threadIdx.x;
    int i = c * 1024 + tid;
    int v = (i < N) ? cbase[i] : 0;
    s[tid] = v;
    __syncthreads();
    #pragma unroll
    for (int o = 1; o < 1024; o <<= 1) {
        int t = (tid >= o) ? s[tid - o] : 0;
        __syncthreads();
        s[tid] += t;
        __syncthreads();
    }
    if (i < N) obase[i] = s[tid] - v;
    if (tid == 1023) chunksum[bid] = s[1023];
}

__global__ void scanB(const int* __restrict__ chunksum, int* __restrict__ chunkbase,
                      int* __restrict__ off)
{
    int t = threadIdx.x;
    if (t == 0) {
        int b = 0;
        for (int c = 0; c < CH0; ++c) { chunkbase[c] = b; b += chunksum[c]; }
        off[NP] = b;
    } else if (t == 1) {
        int b = 0;
        for (int c = 0; c < CH1; ++c) { chunkbase[CH0 + c] = b; b += chunksum[CH0 + c]; }
        off[NP + 1 + NP] = b;
    } else if (t == 2) {
        int b = 0;
        for (int c = 0; c < CH2; ++c) { chunkbase[CH0 + CH1 + c] = b; b += chunksum[CH0 + CH1 + c]; }
        off[2 * NP + 2 + NL] = b;
    }
}

__global__ __launch_bounds__(1024) void scanC(int* __restrict__ off,
                                              const int* __restrict__ chunkbase,
                                              int* __restrict__ cur)
{
    int bid = blockIdx.x;
    int* obase; int* curb; int N; int c;
    if (bid < CH0)            { obase = off;              curb = cur;          N = NP; c = bid; }
    else if (bid < CH0 + CH1) { obase = off + NP + 1;     curb = cur + NP;     N = NP; c = bid - CH0; }
    else                      { obase = off + 2 * NP + 2; curb = cur + 2 * NP; N = NL; c = bid - CH0 - CH1; }
    int i = c * 1024 + threadIdx.x;
    if (i < N) {
        int v = obase[i] + chunkbase[bid];
        obase[i] = v;
        curb[i] = v;
    }
}

__global__ void scatter_all(const int* __restrict__ ei_pp, const float* __restrict__ ea_pp,
                            const int* __restrict__ ei_lp, const float* __restrict__ ea_lp,
                            const int* __restrict__ ei_pl, const float* __restrict__ ea_pl,
                            int* __restrict__ cur, int* __restrict__ ssrc,
                            float* __restrict__ su)
{
    const float usc = (float)NBIN / 8.0f;
    int idx = blockIdx.x * blockDim.x + threadIdx.x;
    if (idx >= ETOT) return;
    if (idx < EPP) {
        int e = idx;
        int d = ei_pp[EPP + e];
        int p = atomicAdd(&cur[d], 1);
        ssrc[p] = ei_pp[e];
        su[p] = ea_pp[e] * usc;
    } else if (idx < EPP + ELP) {
        int e = idx - EPP;
        int d = ei_lp[ELP + e];
        int p = EPP + atomicAdd(&cur[NP + d], 1);
        ssrc[p] = ei_lp[e];
        su[p] = ea_lp[e] * usc;
    } else {
        int e = idx - EPP - ELP;
        int d = ei_pl[EPL + e];
        int p = EPP + ELP + atomicAdd(&cur[2 * NP + d], 1);
        ssrc[p] = ei_pl[e];
        su[p] = ea_pl[e] * usc;
    }
}

// ---------------- LUT build: fp16 interleaved (lo, hi) ----------------
__global__ __launch_bounds__(256) void lut_build(
    const float* __restrict__ Wf, const float* __restrict__ Ws, __half2* __restrict__ Th)
{
    int b = blockIdx.x;
    int lt = blockIdx.y;
    int j = threadIdx.x;
    const float step = 8.0f / 15.0f;
    const float coeff = -0.5f / (step * step);
    const float* W = (j < 128 ? Wf : Ws) + ((size_t)lt * 272 + 256) * H + (j & 127);
    float accL = 0.f, accH = 0.f;
    float dL = (float)b * (8.0f / (float)NBIN);
    float dH = (float)(b + 1) * (8.0f / (float)NBIN);
    #pragma unroll
    for (int k = 0; k < 16; ++k) {
        float w = W[(size_t)k * H];
        float dltL = dL - (float)k * step;
        float dltH = dH - (float)k * step;
        accL += __expf(coeff * dltL * dltL) * w;
        accH += __expf(coeff * dltH * dltH) * w;
    }
    Th[((size_t)lt * NBIN + b) * 256 + j] = __floats2half2_rn(accL, accH);
}

// ---------------- fp16 weight pre-convert ----------------
__global__ __launch_bounds__(128) void wconv(
    const float* __restrict__ Wf, const float* __restrict__ Ws, __half* __restrict__ Wh)
{
    const int bmap[12] = {0, 0, 0, 0, 1, 1, 2, 2, 1, 1, 2, 2};
    const int rmap[12] = {0, 0, 128, 128, 0, 0, 128, 128, 128, 128, 0, 0};
    const int fmap[12] = {1, 0, 1, 0, 1, 0, 1, 0, 1, 0, 1, 0};
    int ls = blockIdx.x;
    int layer = ls / 12, s = ls % 12;
    int k = blockIdx.y;
    int n = threadIdx.x;
    const float* base = fmap[s] ? Wf : Ws;
    float v = base[((size_t)(layer * 3 + bmap[s]) * 272 + rmap[s] + k) * H + n];
    Wh[((size_t)ls * 128 + n) * 128 + k] = __float2half(v);
}

// ---------------- merged initial embedding ----------------
__global__ __launch_bounds__(128) void embed_kernel(
    const float* __restrict__ xp, const float* __restrict__ Wp, const float* __restrict__ bp,
    const float* __restrict__ xl, const float* __restrict__ Wl, const float* __restrict__ bl,
    float* __restrict__ outp, float* __restrict__ outl,
    __half* __restrict__ outph, __half* __restrict__ outlh)
{
    int i = blockIdx.x;
    int j = threadIdx.x;
    const float *x, *W, *b; float* o; __half* oh; int r;
    if (i < NP) { x = xp; W = Wp; b = bp; o = outp; oh = outph; r = i; }
    else        { x = xl; W = Wl; b = bl; o = outl; oh = outlh; r = i - NP; }
    const float* xr = x + (size_t)r * 6;
    float acc = b[j];
    #pragma unroll
    for (int k = 0; k < 6; ++k) acc += xr[k] * W[k * H + j];
    o[(size_t)r * H + j] = acc;
    oh[(size_t)r * H + j] = __float2half(acc);
}

// ---------------- pipelined fp16 mma GEMM with ldmatrix ----------------
#define APH 72
#define ASTH (128 * APH)
#define BSTH (128 * APH)
#define STGH (ASTH + BSTH)
#define SMEM_MMA_BYTES (2 * STGH * 2)

__global__ __launch_bounds__(256, 2) void proj_mma(
    const __half* __restrict__ Xph, const __half* __restrict__ Xlh,
    const __half* __restrict__ Wh,
    __half* __restrict__ outP, __half* __restrict__ outL)
{
    int slice = blockIdx.y;
    const __half* Xh; __half* out; int N, outStride, col;
    if (slice < 8) { Xh = Xph; out = outP; N = NP; outStride = 8 * H; col = slice; }
    else           { Xh = Xlh; out = outL; N = NL; outStride = 4 * H; col = slice - 8; }
    int m0 = blockIdx.x * 128;
    if (m0 >= N) return;

    extern __shared__ __half smh[];
    uint32_t smb = smem_u32(smh);
    const __half* Whs = Wh + (size_t)slice * 128 * 128;
    int tid = threadIdx.x;
    int lane = tid & 31, warp = tid >> 5;
    int g = lane >> 2, t = lane & 3;

    auto load_stage = [&](int chunk, int s) {
        int kb = chunk * 64;
        uint32_t abase = smb + (uint32_t)(s * STGH) * 2u;
        uint32_t bbase = abase + (uint32_t)ASTH * 2u;
        #pragma unroll
        for (int i = 0; i < 4; ++i) {
            int idx = tid + i * 256;
            int r = idx >> 3, c8 = (idx & 7) * 8;
            uint32_t dst = abase + (uint32_t)(r * APH + c8) * 2u;
            const __half* src = Xh + (size_t)(m0 + r) * H + kb + c8;
            int sz = (m0 + r < N) ? 16 : 0;
            asm volatile("cp.async.cg.shared.global [%0], [%1], 16, %2;"
                         :: "r"(dst), "l"(src), "r"(sz));
        }
        #pragma unroll
        for (int i = 0; i < 4; ++i) {
            int idx = tid + i * 256;
            int n = idx >> 3, k8 = (idx & 7) * 8;
            uint32_t dst = bbase + (uint32_t)(n * APH + k8) * 2u;
            const __half* src = Whs + (size_t)n * 128 + kb + k8;
            asm volatile("cp.async.cg.shared.global [%0], [%1], 16;"
                         :: "r"(dst), "l"(src));
        }
        asm volatile("cp.async.commit_group;" ::: "memory");
    };

    load_stage(0, 0);
    load_stage(1, 1);

    int wm = warp >> 2;
    int wn = warp & 3;
    int mbase = wm * 64;
    int nbase = wn * 32;

    int a_row = lane & 15;
    int a_kh = (lane >> 4) * 8;
    int b_nrow = (lane >> 4) * 8 + (lane & 7);
    int b_kh = ((lane >> 3) & 1) * 8;

    float d[4][4][4];
    #pragma unroll
    for (int i = 0; i < 4; ++i)
        #pragma unroll
        for (int j = 0; j < 4; ++j)
            #pragma unroll
            for (int q = 0; q < 4; ++q) d[i][j][q] = 0.f;

    #pragma unroll
    for (int c = 0; c < 2; ++c) {
        if (c == 0) asm volatile("cp.async.wait_group 1;" ::: "memory");
        else        asm volatile("cp.async.wait_group 0;" ::: "memory");
        __syncthreads();

        uint32_t abase = smb + (uint32_t)(c * STGH) * 2u;
        uint32_t bbase = abase + (uint32_t)ASTH * 2u;

        #pragma unroll
        for (int ks = 0; ks < 4; ++ks) {
            int kbl = ks * 16;
            uint32_t a[4][4];
            #pragma unroll
            for (int i = 0; i < 4; ++i) {
                uint32_t addr = abase +
                    (uint32_t)((mbase + i * 16 + a_row) * APH + kbl + a_kh) * 2u;
                ldsm_x4(a[i][0], a[i][1], a[i][2], a[i][3], addr);
            }
            uint32_t b[4][2];
            #pragma unroll
            for (int jp = 0; jp < 2; ++jp) {
                uint32_t addr = bbase +
                    (uint32_t)((nbase + jp * 16 + b_nrow) * APH + kbl + b_kh) * 2u;
                ldsm_x4(b[2 * jp][0], b[2 * jp][1], b[2 * jp + 1][0], b[2 * jp + 1][1], addr);
            }
            #pragma unroll
            for (int i = 0; i < 4; ++i)
                #pragma unroll
                for (int j = 0; j < 4; ++j) {
                    asm volatile(
                        "mma.sync.aligned.m16n8k16.row.col.f32.f16.f16.f32 "
                        "{%0,%1,%2,%3}, {%4,%5,%6,%7}, {%8,%9}, {%0,%1,%2,%3};"
                        : "+f"(d[i][j][0]), "+f"(d[i][j][1]), "+f"(d[i][j][2]), "+f"(d[i][j][3])
                        : "r"(a[i][0]), "r"(a[i][1]), "r"(a[i][2]), "r"(a[i][3]),
                          "r"(b[j][0]), "r"(b[j][1]));
                }
        }
    }

    size_t colbase = (size_t)col * H;
    #pragma unroll
    for (int i = 0; i < 4; ++i) {
        int gr0 = m0 + mbase + i * 16 + g;
        int gr1 = gr0 + 8;
        #pragma unroll
        for (int j = 0; j < 4; ++j) {
            int gc = nbase + j * 8 + t * 2;
            if (gr0 < N)
                *(__half2*)(out + (size_t)gr0 * outStride + colbase + gc) =
                    __floats2half2_rn(d[i][j][0], d[i][j][1]);
            if (gr1 < N)
                *(__half2*)(out + (size_t)gr1 * outStride + colbase + gc) =
                    __floats2half2_rn(d[i][j][2], d[i][j][3]);
        }
    }
}

// ---------------- fused edge + node-update kernel: warp per node ----------------
struct FusedArgs {
    const int*    off[3];
    const int*    ssrc[3];
    const float*  su[3];
    const __half2* T[3];
    const __half* Pd[3]; int dstr[3];
    const __half* Ps[3]; int sstr[3];
    const float*  bfp[3];
    const float*  bsp[3];
    const float*  bn_w; const float* bn_b;
    const float*  ln_w; const float* ln_b;
    int layer;
    const float*  xp_in; const float* xl_in;
    float* xp_out; float* xl_out;
    __half* xph_out; __half* xlh_out;
};

__device__ __forceinline__ void edge_math(
    float4 fsv, float4 ssv, float u, const __half2* __restrict__ T, int j0,
    float fd0, float fd1, float fd2, float fd3,
    float sd0, float sd1, float sd2, float sd3,
    float& a0, float& a1, float& a2, float& a3, bool valid)
{
    int b = min((int)u, NBIN - 1);
    float w = u - (float)b;
    const __half2* Tb = T + (size_t)b * 256 + j0;
    uint4 fv = *(const uint4*)(Tb);
    uint4 sv = *(const uint4*)(Tb + 128);
    float2 f0p = __half22float2(*(__half2*)&fv.x);
    float2 f1p = __half22float2(*(__half2*)&fv.y);
    float2 f2p = __half22float2(*(__half2*)&fv.z);
    float2 f3p = __half22float2(*(__half2*)&fv.w);
    float2 s0p = __half22float2(*(__half2*)&sv.x);
    float2 s1p = __half22float2(*(__half2*)&sv.y);
    float2 s2p = __half22float2(*(__half2*)&sv.z);
    float2 s3p = __half22float2(*(__half2*)&sv.w);

    float f0 = fd0 + fsv.x + f0p.x + w * (f0p.y - f0p.x);
    float f1 = fd1 + fsv.y + f1p.x + w * (f1p.y - f1p.x);
    float f2 = fd2 + fsv.z + f2p.x + w * (f2p.y - f2p.x);
    float f3 = fd3 + fsv.w + f3p.x + w * (f3p.y - f3p.x);
    float s0 = sd0 + ssv.x + s0p.x + w * (s0p.y - s0p.x);
    float s1 = sd1 + ssv.y + s1p.x + w * (s1p.y - s1p.x);
    float s2 = sd2 + ssv.z + s2p.x + w * (s2p.y - s2p.x);
    float s3 = sd3 + ssv.w + s3p.x + w * (s3p.y - s3p.x);

    if (valid) {
        a0 += sig_tanh(f0) * softplus_f(s0);
        a1 += sig_tanh(f1) * softplus_f(s1);
        a2 += sig_tanh(f2) * softplus_f(s2);
        a3 += sig_tanh(f3) * softplus_f(s3);
    }
}

__device__ __forceinline__ float4 edge_accum(
    const FusedArgs& fa, int t, int n, int j0)
{
    const int* off = fa.off[t];
    int p0 = off[n], p1 = off[n + 1];

    float4 bf4 = *(const float4*)(fa.bfp[t] + j0);
    float4 bs4 = *(const float4*)(fa.bsp[t] + j0);
    const __half* pd = fa.Pd[t] + (size_t)n * fa.dstr[t] + j0;
    float4 fdv = h4f(*(const uint2*)(pd));
    float4 sdv = h4f(*(const uint2*)(pd + H));
    float fd0 = fdv.x + bf4.x, fd1 = fdv.y + bf4.y, fd2 = fdv.z + bf4.z, fd3 = fdv.w + bf4.w;
    float sd0 = sdv.x + bs4.x, sd1 = sdv.y + bs4.y, sd2 = sdv.z + bs4.z, sd3 = sdv.w + bs4.w;

    const __half* Ps = fa.Ps[t];
    int sstr = fa.sstr[t];
    const int* ssrc = fa.ssrc[t];
    const float* su = fa.su[t];
    const __half2* T = fa.T[t];

    float a0 = 0.f, a1 = 0.f, a2 = 0.f, a3 = 0.f;

    for (int p = p0; p < p1; p += 4) {
        int pe = p1 - 1;
        int i1 = min(p + 1, pe), i2 = min(p + 2, pe), i3 = min(p + 3, pe);
        int sA = ssrc[p], sB = ssrc[i1], sC = ssrc[i2], sD = ssrc[i3];
        float uA = su[p], uB = su[i1], uC = su[i2], uD = su[i3];

        const __half* qA = Ps + (size_t)sA * sstr + j0;
        const __half* qB = Ps + (size_t)sB * sstr + j0;
        const __half* qC = Ps + (size_t)sC * sstr + j0;
        const __half* qD = Ps + (size_t)sD * sstr + j0;
        uint2 rfA = *(const uint2*)(qA);
        uint2 rfB = *(const uint2*)(qB);
        uint2 rfC = *(const uint2*)(qC);
        uint2 rfD = *(const uint2*)(qD);
        uint2 rsA = *(const uint2*)(qA + H);
        uint2 rsB = *(const uint2*)(qB + H);
        uint2 rsC = *(const uint2*)(qC + H);
        uint2 rsD = *(const uint2*)(qD + H);

        edge_math(h4f(rfA), h4f(rsA), uA, T, j0, fd0, fd1, fd2, fd3, sd0, sd1, sd2, sd3,
                  a0, a1, a2, a3, true);
        edge_math(h4f(rfB), h4f(rsB), uB, T, j0, fd0, fd1, fd2, fd3, sd0, sd1, sd2, sd3,
                  a0, a1, a2, a3, p + 1 < p1);
        edge_math(h4f(rfC), h4f(rsC), uC, T, j0, fd0, fd1, fd2, fd3, sd0, sd1, sd2, sd3,
                  a0, a1, a2, a3, p + 2 < p1);
        edge_math(h4f(rfD), h4f(rsD), uD, T, j0, fd0, fd1, fd2, fd3, sd0, sd1, sd2, sd3,
                  a0, a1, a2, a3, p + 3 < p1);
    }
    return make_float4(a0, a1, a2, a3);
}

__device__ __forceinline__ float4 bn_res(float4 g, float4 x, const float* bnw,
                                         const float* bnb, int j0)
{
    const float bnf = rsqrtf(1.0f + 1e-5f);
    float4 bw = *(const float4*)(bnw + j0);
    float4 bb = *(const float4*)(bnb + j0);
    float4 a;
    a.x = g.x * (bw.x * bnf) + bb.x + x.x;
    a.y = g.y * (bw.y * bnf) + bb.y + x.y;
    a.z = g.z * (bw.z * bnf) + bb.z + x.z;
    a.w = g.w * (bw.w * bnf) + bb.w + x.w;
    return a;
}

__global__ __launch_bounds__(256) void edge_update(FusedArgs fa)
{
    int w = blockIdx.x * 8 + (threadIdx.x >> 5);
    int lane = threadIdx.x & 31;
    int j0 = lane * 4;
    int l = fa.layer;

    if (w < NP) {
        int n = w;
        float4 g1 = edge_accum(fa, 0, n, j0);   // pp
        float4 g2 = edge_accum(fa, 1, n, j0);   // lp

        size_t off = (size_t)n * H + j0;
        float4 x = *(const float4*)(fa.xp_in + off);

        size_t pb0 = (size_t)(l * 3 + 0) * H;
        float4 a1 = bn_res(g1, x, fa.bn_w + pb0, fa.bn_b + pb0, j0);
        float4 y1 = cg_ln_relu(a1, *(const float4*)(fa.ln_w + pb0 + j0),
                               *(const float4*)(fa.ln_b + pb0 + j0));
        size_t pb1 = (size_t)(l * 3 + 1) * H;
        float4 a2 = bn_res(g2, x, fa.bn_w + pb1, fa.bn_b + pb1, j0);
        float4 y2 = cg_ln_relu(a2, *(const float4*)(fa.ln_w + pb1 + j0),
                               *(const float4*)(fa.ln_b + pb1 + j0));
        float4 r;
        r.x = y1.x + y2.x + 2.f * x.x;
        r.y = y1.y + y2.y + 2.f * x.y;
        r.z = y1.z + y2.z + 2.f * x.z;
        r.w = y1.w + y2.w + 2.f * x.w;
        *(float4*)(fa.xp_out + off) = r;
        *(__half2*)(fa.xph_out + off) = __floats2half2_rn(r.x, r.y);
        *(__half2*)(fa.xph_out + off + 2) = __floats2half2_rn(r.z, r.w);
    } else if (w < NP + NL) {
        int n = w - NP;
        float4 g = edge_accum(fa, 2, n, j0);    // pl

        size_t off = (size_t)n * H + j0;
        float4 x = *(const float4*)(fa.xl_in + off);
        size_t pb2 = (size_t)(l * 3 + 2) * H;
        float4 a = bn_res(g, x, fa.bn_w + pb2, fa.bn_b + pb2, j0);
        float4 y = cg_ln_relu(a, *(const float4*)(fa.ln_w + pb2 + j0),
                              *(const float4*)(fa.ln_b + pb2 + j0));
        float4 r;
        r.x = y.x + x.x; r.y = y.y + x.y; r.z = y.z + x.z; r.w = y.w + x.w;
        *(float4*)(fa.xl_out + off) = r;
        *(__half2*)(fa.xlh_out + off) = __floats2half2_rn(r.x, r.y);
        *(__half2*)(fa.xlh_out + off + 2) = __floats2half2_rn(r.z, r.w);
    }
}

// ---------------- final: warp-per-node LN(xp) @ fc_w + fc_b, shfl-only ----------
__global__ __launch_bounds__(256) void final_kernel(
    const float* __restrict__ xp,
    const float* __restrict__ lnw, const float* __restrict__ lnb,
    const float* __restrict__ fcw, const float* __restrict__ fcb,
    float* __restrict__ out)
{
    int w = blockIdx.x * 8 + (threadIdx.x >> 5);
    int lane = threadIdx.x & 31;
    if (w >= NP) return;
    int j0 = lane * 4;

    float4 x = *(const float4*)(xp + (size_t)w * H + j0);
    float s = x.x + x.y + x.z + x.w;
    float q = x.x * x.x + x.y * x.y + x.z * x.z + x.w * x.w;
    #pragma unroll
    for (int o = 16; o > 0; o >>= 1) {
        s += __shfl_xor_sync(0xffffffffu, s, o);
        q += __shfl_xor_sync(0xffffffffu, q, o);
    }
    float mean = s * (1.0f / H);
    float var = q * (1.0f / H) - mean * mean;
    float rn = rsqrtf(var + 1e-5f);
    float4 lw = *(const float4*)(lnw + j0);
    float4 lb = *(const float4*)(lnb + j0);
    float yv[4];
    yv[0] = (x.x - mean) * rn * lw.x + lb.x;
    yv[1] = (x.y - mean) * rn * lw.y + lb.y;
    yv[2] = (x.z - mean) * rn * lw.z + lb.z;
    yv[3] = (x.w - mean) * rn * lw.w + lb.w;

    int c = (lane < 21) ? lane : 0;
    float acc = fcb[c];
    #pragma unroll
    for (int j = 0; j < 128; ++j) {
        float yj = __shfl_sync(0xffffffffu, yv[j & 3], j >> 2);
        acc += yj * fcw[j * 21 + c];
    }
    if (lane < 21)
        out[(size_t)w * 21 + lane] = acc;
}

// ---------------- host ----------------
extern "C" void kernel_launch(void* const* d_in, const int* in_sizes, int n_in,
                              void* d_out, int out_size)
{
    const float* x_protein = (const float*)d_in[0];
    const float* x_ligand  = (const float*)d_in[1];
    const int*   ei_pp     = (const int*)d_in[2];
    const float* ea_pp     = (const float*)d_in[3];
    const int*   ei_lp     = (const int*)d_in[4];
    const float* ea_lp     = (const float*)d_in[5];
    const int*   ei_pl     = (const int*)d_in[6];
    const float* ea_pl     = (const float*)d_in[7];
    const float* Wp        = (const float*)d_in[8];
    const float* bp        = (const float*)d_in[9];
    const float* Wl        = (const float*)d_in[10];
    const float* bl        = (const float*)d_in[11];
    const float* Wf        = (const float*)d_in[12];
    const float* bf        = (const float*)d_in[13];
    const float* Ws        = (const float*)d_in[14];
    const float* bs        = (const float*)d_in[15];
    const float* bn_w      = (const float*)d_in[16];
    const float* bn_b      = (const float*)d_in[17];
    const float* ln_w      = (const float*)d_in[18];
    const float* ln_b      = (const float*)d_in[19];
    const float* lno_w     = (const float*)d_in[20];
    const float* lno_b     = (const float*)d_in[21];
    const float* fc_w      = (const float*)d_in[22];
    const float* fc_b      = (const float*)d_in[23];
    float* out = (float*)d_out;

    float *xpA, *xpB, *xlA, *xlB, *su;
    __half2 *Th;
    __half *Pp, *Pl, *xph, *xlh, *Wh;
    int *cnt, *offs, *cur, *ssrc, *chs, *chb;
    cudaGetSymbolAddress((void**)&xpA, g_xpA);
    cudaGetSymbolAddress((void**)&xpB, g_xpB);
    cudaGetSymbolAddress((void**)&xlA, g_xlA);
    cudaGetSymbolAddress((void**)&xlB, g_xlB);
    cudaGetSymbolAddress((void**)&xph, g_xph);
    cudaGetSymbolAddress((void**)&xlh, g_xlh);
    cudaGetSymbolAddress((void**)&Wh, g_Wh);
    cudaGetSymbolAddress((void**)&Pp, g_Pp);
    cudaGetSymbolAddress((void**)&Pl, g_Pl);
    cudaGetSymbolAddress((void**)&Th, g_Th);
    cudaGetSymbolAddress((void**)&cnt, g_cnt);
    cudaGetSymbolAddress((void**)&offs, g_off);
    cudaGetSymbolAddress((void**)&cur, g_cur);
    cudaGetSymbolAddress((void**)&ssrc, g_ssrc);
    cudaGetSymbolAddress((void**)&su, g_su);
    cudaGetSymbolAddress((void**)&chs, g_chunksum);
    cudaGetSymbolAddress((void**)&chb, g_chunkbase);

    cudaFuncSetAttribute(proj_mma, cudaFuncAttributeMaxDynamicSharedMemorySize, SMEM_MMA_BYTES);

    embed_kernel<<<NP + NL, 128>>>(x_protein, Wp, bp, x_ligand, Wl, bl, xpA, xlA, xph, xlh);
    wconv<<<dim3(48, 128), 128>>>(Wf, Ws, Wh);
    lut_build<<<dim3(NBIN, 12), 256>>>(Wf, Ws, Th);
    cudaMemsetAsync(cnt, 0, NCNT * sizeof(int), 0);
    hist_all<<<(ETOT + 255) / 256, 256>>>(ei_pp, ei_lp, ei_pl, cnt);
    proj_mma<<<dim3((NP + 127) / 128, 12), 256, SMEM_MMA_BYTES>>>(xph, xlh, Wh, Pp, Pl);
    scanA<<<CHT, 1024>>>(cnt, offs, chs);
    scanB<<<1, 32>>>(chs, chb, offs);
    scanC<<<CHT, 1024>>>(offs, chb, cur);
    scatter_all<<<(ETOT + 255) / 256, 256>>>(ei_pp, ea_pp, ei_lp, ea_lp, ei_pl, ea_pl,
                                             cur, ssrc, su);

    float* xp_cur = xpA; float* xp_nxt = xpB;
    float* xl_cur = xlA; float* xl_nxt = xlB;

    for (int l = 0; l < NLAYER; ++l) {
        if (l > 0)
            proj_mma<<<dim3((NP + 127) / 128, 12), 256, SMEM_MMA_BYTES>>>(
                xph, xlh, Wh + (size_t)l * 12 * 128 * 128, Pp, Pl);

        FusedArgs fa;
        fa.off[0] = offs;              fa.ssrc[0] = ssrc;             fa.su[0] = su;
        fa.T[0] = Th + (size_t)(l * 3 + 0) * NBIN * 256;
        fa.Pd[0] = Pp + 0 * H; fa.dstr[0] = 8 * H;
        fa.Ps[0] = Pp + 2 * H; fa.sstr[0] = 8 * H;
        fa.bfp[0] = bf + (size_t)(l * 3 + 0) * H; fa.bsp[0] = bs + (size_t)(l * 3 + 0) * H;
        fa.off[1] = offs + NP + 1;     fa.ssrc[1] = ssrc + EPP;       fa.su[1] = su + EPP;
        fa.T[1] = Th + (size_t)(l * 3 + 1) * NBIN * 256;
        fa.Pd[1] = Pp + 4 * H; fa.dstr[1] = 8 * H;
        fa.Ps[1] = Pl + 0 * H; fa.sstr[1] = 4 * H;
        fa.bfp[1] = bf + (size_t)(l * 3 + 1) * H; fa.bsp[1] = bs + (size_t)(l * 3 + 1) * H;
        fa.off[2] = offs + 2 * NP + 2; fa.ssrc[2] = ssrc + EPP + ELP; fa.su[2] = su + EPP + ELP;
        fa.T[2] = Th + (size_t)(l * 3 + 2) * NBIN * 256;
        fa.Pd[2] = Pl + 2 * H; fa.dstr[2] = 4 * H;
        fa.Ps[2] = Pp + 6 * H; fa.sstr[2] = 8 * H;
        fa.bfp[2] = bf + (size_t)(l * 3 + 2) * H; fa.bsp[2] = bs + (size_t)(l * 3 + 2) * H;
        fa.bn_w = bn_w; fa.bn_b = bn_b; fa.ln_w = ln_w; fa.ln_b = ln_b;
        fa.layer = l;
        fa.xp_in = xp_cur; fa.xl_in = xl_cur;
        fa.xp_out = xp_nxt; fa.xl_out = xl_nxt;
        fa.xph_out = xph; fa.xlh_out = xlh;

        edge_update<<<(NP + NL + 7) / 8, 256>>>(fa);

        float* t;
        t = xp_cur; xp_cur = xp_nxt; xp_nxt = t;
        t = xl_cur; xl_cur = xl_nxt; xl_nxt = t;
    }

    final_kernel<<<(NP + 7) / 8, 256>>>(xp_cur, lno_w, lno_b, fc_w, fc_b, out);
}

// round 16
// speedup vs baseline: 1.2203x; 1.0107x over previous
#include <cuda_runtime.h>
#include <cuda_fp16.h>
#include <cstdint>
#include <cstddef>

#define NP 50000
#define NL 10000
#define H  128
#define D  16
#define NLAYER 4
#define EPP 500000
#define ELP 100000
#define EPL 100000
#define ETOT (EPP + ELP + EPL)
#define NCNT (2 * NP + NL)
#define NBIN 256
#define CH0 49
#define CH1 49
#define CH2 10
#define CHT (CH0 + CH1 + CH2)

// ---------------- scratch (device globals; no runtime allocation) ----------------
__device__ float  g_xpA[NP * H];
__device__ float  g_xpB[NP * H];
__device__ float  g_xlA[NL * H];
__device__ float  g_xlB[NL * H];
__device__ __align__(16) __half g_xph[NP * H];
__device__ __align__(16) __half g_xlh[NL * H];
__device__ __align__(16) __half g_Wh[(size_t)48 * 128 * 128];
__device__ __align__(16) __half g_Pp[(size_t)NP * 8 * H];   // f|s pairs adjacent (+0/+H)
__device__ __align__(16) __half g_Pl[(size_t)NL * 4 * H];
// fp16 interleaved LUT: Th[lt][bin][col] = (T(bin), T(bin+1))
__device__ __align__(16) __half2 g_Th[(size_t)12 * NBIN * 256];
__device__ int    g_cnt[NCNT];
__device__ int    g_off[NCNT + 3];
__device__ int    g_cur[NCNT];
__device__ int    g_ssrc[ETOT];
__device__ float  g_su[ETOT];
__device__ int    g_chunksum[CHT];
__device__ int    g_chunkbase[CHT];

// ---------------- small helpers ----------------
__device__ __forceinline__ uint32_t smem_u32(const void* p) {
    uint32_t a;
    asm("{ .reg .u64 t; cvta.to.shared.u64 t, %1; cvt.u32.u64 %0, t; }" : "=r"(a) : "l"(p));
    return a;
}
__device__ __forceinline__ void ldsm_x4(uint32_t& r0, uint32_t& r1, uint32_t& r2, uint32_t& r3,
                                        uint32_t addr) {
    asm volatile("ldmatrix.sync.aligned.m8n8.x4.shared.b16 {%0,%1,%2,%3}, [%4];"
                 : "=r"(r0), "=r"(r1), "=r"(r2), "=r"(r3) : "r"(addr));
}
__device__ __forceinline__ float sig_tanh(float x) {
    float t;
    asm("tanh.approx.f32 %0, %1;" : "=f"(t) : "f"(x * 0.5f));
    return 0.5f * t + 0.5f;
}
__device__ __forceinline__ float softplus_f(float x) {
    return fmaxf(x, 0.f) + __logf(1.0f + __expf(-fabsf(x)));
}
__device__ __forceinline__ float4 h4f(uint2 v) {
    __half2 a = *(__half2*)&v.x;
    __half2 b = *(__half2*)&v.y;
    float2 fa = __half22float2(a);
    float2 fb = __half22float2(b);
    return make_float4(fa.x, fa.y, fb.x, fb.y);
}
__device__ __forceinline__ float4 cg_ln_relu(float4 a, float4 lw, float4 lb)
{
    float s = a.x + a.y + a.z + a.w;
    float q = a.x * a.x + a.y * a.y + a.z * a.z + a.w * a.w;
    #pragma unroll
    for (int o = 16; o > 0; o >>= 1) {
        s += __shfl_xor_sync(0xffffffffu, s, o);
        q += __shfl_xor_sync(0xffffffffu, q, o);
    }
    float mean = s * (1.0f / H);
    float var = q * (1.0f / H) - mean * mean;
    float r = rsqrtf(var + 1e-5f);
    float4 y;
    y.x = fmaxf((a.x - mean) * r * lw.x + lb.x, 0.f);
    y.y = fmaxf((a.y - mean) * r * lw.y + lb.y, 0.f);
    y.z = fmaxf((a.z - mean) * r * lw.z + lb.z, 0.f);
    y.w = fmaxf((a.w - mean) * r * lw.w + lb.w, 0.f);
    return y;
}

// ---------------- CSR build ----------------
__global__ void hist_all(const int* __restrict__ ei_pp, const int* __restrict__ ei_lp,
                         const int* __restrict__ ei_pl, int* __restrict__ cnt)
{
    int idx = blockIdx.x * blockDim.x + threadIdx.x;
    if (idx >= ETOT) return;
    if (idx < EPP) {
        atomicAdd(&cnt[ei_pp[EPP + idx]], 1);
    } else if (idx < EPP + ELP) {
        int e = idx - EPP;
        atomicAdd(&cnt[NP + ei_lp[ELP + e]], 1);
    } else {
        int e = idx - EPP - ELP;
        atomicAdd(&cnt[2 * NP + ei_pl[EPL + e]], 1);
    }
}

__global__ __launch_bounds__(1024) void scanA(const int* __restrict__ cnt,
                                              int* __restrict__ off,
                                              int* __restrict__ chunksum)
{
    __shared__ int s[1024];
    int bid = blockIdx.x;
    const int* cbase; int* obase; int N; int c;
    if (bid < CH0)            { cbase = cnt;          obase = off;              N = NP; c = bid; }
    else if (bid < CH0 + CH1) { cbase = cnt + NP;     obase = off + NP + 1;     N = NP; c = bid - CH0; }
    else                      { cbase = cnt + 2 * NP; obase = off + 2 * NP + 2; N = NL; c = bid - CH0 - CH1; }
    int tid = threadIdx.x;
    int i = c * 1024 + tid;
    int v = (i < N) ? cbase[i] : 0;
    s[tid] = v;
    __syncthreads();
    #pragma unroll
    for (int o = 1; o < 1024; o <<= 1) {
        int t = (tid >= o) ? s[tid - o] : 0;
        __syncthreads();
        s[tid] += t;
        __syncthreads();
    }
    if (i < N) obase[i] = s[tid] - v;
    if (tid == 1023) chunksum[bid] = s[1023];
}

__global__ void scanB(const int* __restrict__ chunksum, int* __restrict__ chunkbase,
                      int* __restrict__ off)
{
    int t = threadIdx.x;
    if (t == 0) {
        int b = 0;
        for (int c = 0; c < CH0; ++c) { chunkbase[c] = b; b += chunksum[c]; }
        off[NP] = b;
    } else if (t == 1) {
        int b = 0;
        for (int c = 0; c < CH1; ++c) { chunkbase[CH0 + c] = b; b += chunksum[CH0 + c]; }
        off[NP + 1 + NP] = b;
    } else if (t == 2) {
        int b = 0;
        for (int c = 0; c < CH2; ++c) { chunkbase[CH0 + CH1 + c] = b; b += chunksum[CH0 + CH1 + c]; }
        off[2 * NP + 2 + NL] = b;
    }
}

__global__ __launch_bounds__(1024) void scanC(int* __restrict__ off,
                                              const int* __restrict__ chunkbase,
                                              int* __restrict__ cur)
{
    int bid = blockIdx.x;
    int* obase; int* curb; int N; int c;
    if (bid < CH0)            { obase = off;              curb = cur;          N = NP; c = bid; }
    else if (bid < CH0 + CH1) { obase = off + NP + 1;     curb = cur + NP;     N = NP; c = bid - CH0; }
    else                      { obase = off + 2 * NP + 2; curb = cur + 2 * NP; N = NL; c = bid - CH0 - CH1; }
    int i = c * 1024 + threadIdx.x;
    if (i < N) {
        int v = obase[i] + chunkbase[bid];
        obase[i] = v;
        curb[i] = v;
    }
}

__global__ void scatter_all(const int* __restrict__ ei_pp, const float* __restrict__ ea_pp,
                            const int* __restrict__ ei_lp, const float* __restrict__ ea_lp,
                            const int* __restrict__ ei_pl, const float* __restrict__ ea_pl,
                            int* __restrict__ cur, int* __restrict__ ssrc,
                            float* __restrict__ su)
{
    const float usc = (float)NBIN / 8.0f;
    int idx = blockIdx.x * blockDim.x + threadIdx.x;
    if (idx >= ETOT) return;
    if (idx < EPP) {
        int e = idx;
        int d = ei_pp[EPP + e];
        int p = atomicAdd(&cur[d], 1);
        ssrc[p] = ei_pp[e];
        su[p] = ea_pp[e] * usc;
    } else if (idx < EPP + ELP) {
        int e = idx - EPP;
        int d = ei_lp[ELP + e];
        int p = EPP + atomicAdd(&cur[NP + d], 1);
        ssrc[p] = ei_lp[e];
        su[p] = ea_lp[e] * usc;
    } else {
        int e = idx - EPP - ELP;
        int d = ei_pl[EPL + e];
        int p = EPP + ELP + atomicAdd(&cur[2 * NP + d], 1);
        ssrc[p] = ei_pl[e];
        su[p] = ea_pl[e] * usc;
    }
}

// ---------------- LUT build: fp16 interleaved (lo, hi) ----------------
__global__ __launch_bounds__(256) void lut_build(
    const float* __restrict__ Wf, const float* __restrict__ Ws, __half2* __restrict__ Th)
{
    int b = blockIdx.x;
    int lt = blockIdx.y;
    int j = threadIdx.x;
    const float step = 8.0f / 15.0f;
    const float coeff = -0.5f / (step * step);
    const float* W = (j < 128 ? Wf : Ws) + ((size_t)lt * 272 + 256) * H + (j & 127);
    float accL = 0.f, accH = 0.f;
    float dL = (float)b * (8.0f / (float)NBIN);
    float dH = (float)(b + 1) * (8.0f / (float)NBIN);
    #pragma unroll
    for (int k = 0; k < 16; ++k) {
        float w = W[(size_t)k * H];
        float dltL = dL - (float)k * step;
        float dltH = dH - (float)k * step;
        accL += __expf(coeff * dltL * dltL) * w;
        accH += __expf(coeff * dltH * dltH) * w;
    }
    Th[((size_t)lt * NBIN + b) * 256 + j] = __floats2half2_rn(accL, accH);
}

// ---------------- fp16 weight pre-convert ----------------
__global__ __launch_bounds__(128) void wconv(
    const float* __restrict__ Wf, const float* __restrict__ Ws, __half* __restrict__ Wh)
{
    const int bmap[12] = {0, 0, 0, 0, 1, 1, 2, 2, 1, 1, 2, 2};
    const int rmap[12] = {0, 0, 128, 128, 0, 0, 128, 128, 128, 128, 0, 0};
    const int fmap[12] = {1, 0, 1, 0, 1, 0, 1, 0, 1, 0, 1, 0};
    int ls = blockIdx.x;
    int layer = ls / 12, s = ls % 12;
    int k = blockIdx.y;
    int n = threadIdx.x;
    const float* base = fmap[s] ? Wf : Ws;
    float v = base[((size_t)(layer * 3 + bmap[s]) * 272 + rmap[s] + k) * H + n];
    Wh[((size_t)ls * 128 + n) * 128 + k] = __float2half(v);
}

// ---------------- merged initial embedding ----------------
__global__ __launch_bounds__(128) void embed_kernel(
    const float* __restrict__ xp, const float* __restrict__ Wp, const float* __restrict__ bp,
    const float* __restrict__ xl, const float* __restrict__ Wl, const float* __restrict__ bl,
    float* __restrict__ outp, float* __restrict__ outl,
    __half* __restrict__ outph, __half* __restrict__ outlh)
{
    int i = blockIdx.x;
    int j = threadIdx.x;
    const float *x, *W, *b; float* o; __half* oh; int r;
    if (i < NP) { x = xp; W = Wp; b = bp; o = outp; oh = outph; r = i; }
    else        { x = xl; W = Wl; b = bl; o = outl; oh = outlh; r = i - NP; }
    const float* xr = x + (size_t)r * 6;
    float acc = b[j];
    #pragma unroll
    for (int k = 0; k < 6; ++k) acc += xr[k] * W[k * H + j];
    o[(size_t)r * H + j] = acc;
    oh[(size_t)r * H + j] = __float2half(acc);
}

// ---------------- pipelined fp16 mma GEMM with ldmatrix ----------------
#define APH 72
#define ASTH (128 * APH)
#define BSTH (128 * APH)
#define STGH (ASTH + BSTH)
#define SMEM_MMA_BYTES (2 * STGH * 2)

__global__ __launch_bounds__(256, 2) void proj_mma(
    const __half* __restrict__ Xph, const __half* __restrict__ Xlh,
    const __half* __restrict__ Wh,
    __half* __restrict__ outP, __half* __restrict__ outL)
{
    int slice = blockIdx.y;
    const __half* Xh; __half* out; int N, outStride, col;
    if (slice < 8) { Xh = Xph; out = outP; N = NP; outStride = 8 * H; col = slice; }
    else           { Xh = Xlh; out = outL; N = NL; outStride = 4 * H; col = slice - 8; }
    int m0 = blockIdx.x * 128;
    if (m0 >= N) return;

    extern __shared__ __half smh[];
    uint32_t smb = smem_u32(smh);
    const __half* Whs = Wh + (size_t)slice * 128 * 128;
    int tid = threadIdx.x;
    int lane = tid & 31, warp = tid >> 5;
    int g = lane >> 2, t = lane & 3;

    auto load_stage = [&](int chunk, int s) {
        int kb = chunk * 64;
        uint32_t abase = smb + (uint32_t)(s * STGH) * 2u;
        uint32_t bbase = abase + (uint32_t)ASTH * 2u;
        #pragma unroll
        for (int i = 0; i < 4; ++i) {
            int idx = tid + i * 256;
            int r = idx >> 3, c8 = (idx & 7) * 8;
            uint32_t dst = abase + (uint32_t)(r * APH + c8) * 2u;
            const __half* src = Xh + (size_t)(m0 + r) * H + kb + c8;
            int sz = (m0 + r < N) ? 16 : 0;
            asm volatile("cp.async.cg.shared.global [%0], [%1], 16, %2;"
                         :: "r"(dst), "l"(src), "r"(sz));
        }
        #pragma unroll
        for (int i = 0; i < 4; ++i) {
            int idx = tid + i * 256;
            int n = idx >> 3, k8 = (idx & 7) * 8;
            uint32_t dst = bbase + (uint32_t)(n * APH + k8) * 2u;
            const __half* src = Whs + (size_t)n * 128 + kb + k8;
            asm volatile("cp.async.cg.shared.global [%0], [%1], 16;"
                         :: "r"(dst), "l"(src));
        }
        asm volatile("cp.async.commit_group;" ::: "memory");
    };

    load_stage(0, 0);
    load_stage(1, 1);

    int wm = warp >> 2;
    int wn = warp & 3;
    int mbase = wm * 64;
    int nbase = wn * 32;

    int a_row = lane & 15;
    int a_kh = (lane >> 4) * 8;
    int b_nrow = (lane >> 4) * 8 + (lane & 7);
    int b_kh = ((lane >> 3) & 1) * 8;

    float d[4][4][4];
    #pragma unroll
    for (int i = 0; i < 4; ++i)
        #pragma unroll
        for (int j = 0; j < 4; ++j)
            #pragma unroll
            for (int q = 0; q < 4; ++q) d[i][j][q] = 0.f;

    #pragma unroll
    for (int c = 0; c < 2; ++c) {
        if (c == 0) asm volatile("cp.async.wait_group 1;" ::: "memory");
        else        asm volatile("cp.async.wait_group 0;" ::: "memory");
        __syncthreads();

        uint32_t abase = smb + (uint32_t)(c * STGH) * 2u;
        uint32_t bbase = abase + (uint32_t)ASTH * 2u;

        #pragma unroll
        for (int ks = 0; ks < 4; ++ks) {
            int kbl = ks * 16;
            uint32_t a[4][4];
            #pragma unroll
            for (int i = 0; i < 4; ++i) {
                uint32_t addr = abase +
                    (uint32_t)((mbase + i * 16 + a_row) * APH + kbl + a_kh) * 2u;
                ldsm_x4(a[i][0], a[i][1], a[i][2], a[i][3], addr);
            }
            uint32_t b[4][2];
            #pragma unroll
            for (int jp = 0; jp < 2; ++jp) {
                uint32_t addr = bbase +
                    (uint32_t)((nbase + jp * 16 + b_nrow) * APH + kbl + b_kh) * 2u;
                ldsm_x4(b[2 * jp][0], b[2 * jp][1], b[2 * jp + 1][0], b[2 * jp + 1][1], addr);
            }
            #pragma unroll
            for (int i = 0; i < 4; ++i)
                #pragma unroll
                for (int j = 0; j < 4; ++j) {
                    asm volatile(
                        "mma.sync.aligned.m16n8k16.row.col.f32.f16.f16.f32 "
                        "{%0,%1,%2,%3}, {%4,%5,%6,%7}, {%8,%9}, {%0,%1,%2,%3};"
                        : "+f"(d[i][j][0]), "+f"(d[i][j][1]), "+f"(d[i][j][2]), "+f"(d[i][j][3])
                        : "r"(a[i][0]), "r"(a[i][1]), "r"(a[i][2]), "r"(a[i][3]),
                          "r"(b[j][0]), "r"(b[j][1]));
                }
        }
    }

    size_t colbase = (size_t)col * H;
    #pragma unroll
    for (int i = 0; i < 4; ++i) {
        int gr0 = m0 + mbase + i * 16 + g;
        int gr1 = gr0 + 8;
        #pragma unroll
        for (int j = 0; j < 4; ++j) {
            int gc = nbase + j * 8 + t * 2;
            if (gr0 < N)
                *(__half2*)(out + (size_t)gr0 * outStride + colbase + gc) =
                    __floats2half2_rn(d[i][j][0], d[i][j][1]);
            if (gr1 < N)
                *(__half2*)(out + (size_t)gr1 * outStride + colbase + gc) =
                    __floats2half2_rn(d[i][j][2], d[i][j][3]);
        }
    }
}

// ---------------- fused edge + node-update kernel: warp per node ----------------
struct FusedArgs {
    const int*    off[3];
    const int*    ssrc[3];
    const float*  su[3];
    const __half2* T[3];
    const __half* Pd[3]; int dstr[3];
    const __half* Ps[3]; int sstr[3];
    const float*  bfp[3];
    const float*  bsp[3];
    const float*  bn_w; const float* bn_b;
    const float*  ln_w; const float* ln_b;
    int layer;
    const float*  xp_in; const float* xl_in;
    float* xp_out; float* xl_out;
    __half* xph_out; __half* xlh_out;
};

__device__ __forceinline__ void edge_math(
    float4 fsv, float4 ssv, float u, const __half2* __restrict__ T, int j0,
    float fd0, float fd1, float fd2, float fd3,
    float sd0, float sd1, float sd2, float sd3,
    float& a0, float& a1, float& a2, float& a3, bool valid)
{
    int b = min((int)u, NBIN - 1);
    float w = u - (float)b;
    const __half2* Tb = T + (size_t)b * 256 + j0;
    uint4 fv = *(const uint4*)(Tb);
    uint4 sv = *(const uint4*)(Tb + 128);
    float2 f0p = __half22float2(*(__half2*)&fv.x);
    float2 f1p = __half22float2(*(__half2*)&fv.y);
    float2 f2p = __half22float2(*(__half2*)&fv.z);
    float2 f3p = __half22float2(*(__half2*)&fv.w);
    float2 s0p = __half22float2(*(__half2*)&sv.x);
    float2 s1p = __half22float2(*(__half2*)&sv.y);
    float2 s2p = __half22float2(*(__half2*)&sv.z);
    float2 s3p = __half22float2(*(__half2*)&sv.w);

    float f0 = fd0 + fsv.x + f0p.x + w * (f0p.y - f0p.x);
    float f1 = fd1 + fsv.y + f1p.x + w * (f1p.y - f1p.x);
    float f2 = fd2 + fsv.z + f2p.x + w * (f2p.y - f2p.x);
    float f3 = fd3 + fsv.w + f3p.x + w * (f3p.y - f3p.x);
    float s0 = sd0 + ssv.x + s0p.x + w * (s0p.y - s0p.x);
    float s1 = sd1 + ssv.y + s1p.x + w * (s1p.y - s1p.x);
    float s2 = sd2 + ssv.z + s2p.x + w * (s2p.y - s2p.x);
    float s3 = sd3 + ssv.w + s3p.x + w * (s3p.y - s3p.x);

    if (valid) {
        a0 += sig_tanh(f0) * softplus_f(s0);
        a1 += sig_tanh(f1) * softplus_f(s1);
        a2 += sig_tanh(f2) * softplus_f(s2);
        a3 += sig_tanh(f3) * softplus_f(s3);
    }
}

__device__ __forceinline__ float4 edge_accum(
    const FusedArgs& fa, int t, int n, int j0)
{
    const int* off = fa.off[t];
    int p0 = off[n], p1 = off[n + 1];

    float4 bf4 = *(const float4*)(fa.bfp[t] + j0);
    float4 bs4 = *(const float4*)(fa.bsp[t] + j0);
    const __half* pd = fa.Pd[t] + (size_t)n * fa.dstr[t] + j0;
    float4 fdv = h4f(*(const uint2*)(pd));
    float4 sdv = h4f(*(const uint2*)(pd + H));
    float fd0 = fdv.x + bf4.x, fd1 = fdv.y + bf4.y, fd2 = fdv.z + bf4.z, fd3 = fdv.w + bf4.w;
    float sd0 = sdv.x + bs4.x, sd1 = sdv.y + bs4.y, sd2 = sdv.z + bs4.z, sd3 = sdv.w + bs4.w;

    const __half* Ps = fa.Ps[t];
    int sstr = fa.sstr[t];
    const int* ssrc = fa.ssrc[t];
    const float* su = fa.su[t];
    const __half2* T = fa.T[t];

    float a0 = 0.f, a1 = 0.f, a2 = 0.f, a3 = 0.f;

    for (int p = p0; p < p1; p += 4) {
        int pe = p1 - 1;
        int i1 = min(p + 1, pe), i2 = min(p + 2, pe), i3 = min(p + 3, pe);
        int sA = ssrc[p], sB = ssrc[i1], sC = ssrc[i2], sD = ssrc[i3];
        float uA = su[p], uB = su[i1], uC = su[i2], uD = su[i3];

        const __half* qA = Ps + (size_t)sA * sstr + j0;
        const __half* qB = Ps + (size_t)sB * sstr + j0;
        const __half* qC = Ps + (size_t)sC * sstr + j0;
        const __half* qD = Ps + (size_t)sD * sstr + j0;
        uint2 rfA = *(const uint2*)(qA);
        uint2 rfB = *(const uint2*)(qB);
        uint2 rfC = *(const uint2*)(qC);
        uint2 rfD = *(const uint2*)(qD);
        uint2 rsA = *(const uint2*)(qA + H);
        uint2 rsB = *(const uint2*)(qB + H);
        uint2 rsC = *(const uint2*)(qC + H);
        uint2 rsD = *(const uint2*)(qD + H);

        edge_math(h4f(rfA), h4f(rsA), uA, T, j0, fd0, fd1, fd2, fd3, sd0, sd1, sd2, sd3,
                  a0, a1, a2, a3, true);
        edge_math(h4f(rfB), h4f(rsB), uB, T, j0, fd0, fd1, fd2, fd3, sd0, sd1, sd2, sd3,
                  a0, a1, a2, a3, p + 1 < p1);
        edge_math(h4f(rfC), h4f(rsC), uC, T, j0, fd0, fd1, fd2, fd3, sd0, sd1, sd2, sd3,
                  a0, a1, a2, a3, p + 2 < p1);
        edge_math(h4f(rfD), h4f(rsD), uD, T, j0, fd0, fd1, fd2, fd3, sd0, sd1, sd2, sd3,
                  a0, a1, a2, a3, p + 3 < p1);
    }
    return make_float4(a0, a1, a2, a3);
}

__device__ __forceinline__ float4 bn_res(float4 g, float4 x, const float* bnw,
                                         const float* bnb, int j0)
{
    const float bnf = rsqrtf(1.0f + 1e-5f);
    float4 bw = *(const float4*)(bnw + j0);
    float4 bb = *(const float4*)(bnb + j0);
    float4 a;
    a.x = g.x * (bw.x * bnf) + bb.x + x.x;
    a.y = g.y * (bw.y * bnf) + bb.y + x.y;
    a.z = g.z * (bw.z * bnf) + bb.z + x.z;
    a.w = g.w * (bw.w * bnf) + bb.w + x.w;
    return a;
}

__global__ __launch_bounds__(256) void edge_update(FusedArgs fa)
{
    int w = blockIdx.x * 8 + (threadIdx.x >> 5);
    int lane = threadIdx.x & 31;
    int j0 = lane * 4;
    int l = fa.layer;

    if (w < NP) {
        int n = w;
        float4 g1 = edge_accum(fa, 0, n, j0);   // pp
        float4 g2 = edge_accum(fa, 1, n, j0);   // lp

        size_t off = (size_t)n * H + j0;
        float4 x = *(const float4*)(fa.xp_in + off);

        size_t pb0 = (size_t)(l * 3 + 0) * H;
        float4 a1 = bn_res(g1, x, fa.bn_w + pb0, fa.bn_b + pb0, j0);
        float4 y1 = cg_ln_relu(a1, *(const float4*)(fa.ln_w + pb0 + j0),
                               *(const float4*)(fa.ln_b + pb0 + j0));
        size_t pb1 = (size_t)(l * 3 + 1) * H;
        float4 a2 = bn_res(g2, x, fa.bn_w + pb1, fa.bn_b + pb1, j0);
        float4 y2 = cg_ln_relu(a2, *(const float4*)(fa.ln_w + pb1 + j0),
                               *(const float4*)(fa.ln_b + pb1 + j0));
        float4 r;
        r.x = y1.x + y2.x + 2.f * x.x;
        r.y = y1.y + y2.y + 2.f * x.y;
        r.z = y1.z + y2.z + 2.f * x.z;
        r.w = y1.w + y2.w + 2.f * x.w;
        *(float4*)(fa.xp_out + off) = r;
        *(__half2*)(fa.xph_out + off) = __floats2half2_rn(r.x, r.y);
        *(__half2*)(fa.xph_out + off + 2) = __floats2half2_rn(r.z, r.w);
    } else if (w < NP + NL) {
        int n = w - NP;
        float4 g = edge_accum(fa, 2, n, j0);    // pl

        size_t off = (size_t)n * H + j0;
        float4 x = *(const float4*)(fa.xl_in + off);
        size_t pb2 = (size_t)(l * 3 + 2) * H;
        float4 a = bn_res(g, x, fa.bn_w + pb2, fa.bn_b + pb2, j0);
        float4 y = cg_ln_relu(a, *(const float4*)(fa.ln_w + pb2 + j0),
                              *(const float4*)(fa.ln_b + pb2 + j0));
        float4 r;
        r.x = y.x + x.x; r.y = y.y + x.y; r.z = y.z + x.z; r.w = y.w + x.w;
        *(float4*)(fa.xl_out + off) = r;
        *(__half2*)(fa.xlh_out + off) = __floats2half2_rn(r.x, r.y);
        *(__half2*)(fa.xlh_out + off + 2) = __floats2half2_rn(r.z, r.w);
    }
}

// ---------------- final: warp-per-node LN(xp) @ fc_w + fc_b, shfl-only ----------
__global__ __launch_bounds__(256) void final_kernel(
    const float* __restrict__ xp,
    const float* __restrict__ lnw, const float* __restrict__ lnb,
    const float* __restrict__ fcw, const float* __restrict__ fcb,
    float* __restrict__ out)
{
    int w = blockIdx.x * 8 + (threadIdx.x >> 5);
    int lane = threadIdx.x & 31;
    if (w >= NP) return;
    int j0 = lane * 4;

    float4 x = *(const float4*)(xp + (size_t)w * H + j0);
    float s = x.x + x.y + x.z + x.w;
    float q = x.x * x.x + x.y * x.y + x.z * x.z + x.w * x.w;
    #pragma unroll
    for (int o = 16; o > 0; o >>= 1) {
        s += __shfl_xor_sync(0xffffffffu, s, o);
        q += __shfl_xor_sync(0xffffffffu, q, o);
    }
    float mean = s * (1.0f / H);
    float var = q * (1.0f / H) - mean * mean;
    float rn = rsqrtf(var + 1e-5f);
    float4 lw = *(const float4*)(lnw + j0);
    float4 lb = *(const float4*)(lnb + j0);
    float yv[4];
    yv[0] = (x.x - mean) * rn * lw.x + lb.x;
    yv[1] = (x.y - mean) * rn * lw.y + lb.y;
    yv[2] = (x.z - mean) * rn * lw.z + lb.z;
    yv[3] = (x.w - mean) * rn * lw.w + lb.w;

    int c = (lane < 21) ? lane : 0;
    float acc = fcb[c];
    #pragma unroll
    for (int j = 0; j < 128; ++j) {
        float yj = __shfl_sync(0xffffffffu, yv[j & 3], j >> 2);
        acc += yj * fcw[j * 21 + c];
    }
    if (lane < 21)
        out[(size_t)w * 21 + lane] = acc;
}

// ---------------- host ----------------
extern "C" void kernel_launch(void* const* d_in, const int* in_sizes, int n_in,
                              void* d_out, int out_size)
{
    const float* x_protein = (const float*)d_in[0];
    const float* x_ligand  = (const float*)d_in[1];
    const int*   ei_pp     = (const int*)d_in[2];
    const float* ea_pp     = (const float*)d_in[3];
    const int*   ei_lp     = (const int*)d_in[4];
    const float* ea_lp     = (const float*)d_in[5];
    const int*   ei_pl     = (const int*)d_in[6];
    const float* ea_pl     = (const float*)d_in[7];
    const float* Wp        = (const float*)d_in[8];
    const float* bp        = (const float*)d_in[9];
    const float* Wl        = (const float*)d_in[10];
    const float* bl        = (const float*)d_in[11];
    const float* Wf        = (const float*)d_in[12];
    const float* bf        = (const float*)d_in[13];
    const float* Ws        = (const float*)d_in[14];
    const float* bs        = (const float*)d_in[15];
    const float* bn_w      = (const float*)d_in[16];
    const float* bn_b      = (const float*)d_in[17];
    const float* ln_w      = (const float*)d_in[18];
    const float* ln_b      = (const float*)d_in[19];
    const float* lno_w     = (const float*)d_in[20];
    const float* lno_b     = (const float*)d_in[21];
    const float* fc_w      = (const float*)d_in[22];
    const float* fc_b      = (const float*)d_in[23];
    float* out = (float*)d_out;

    float *xpA, *xpB, *xlA, *xlB, *su;
    __half2 *Th;
    __half *Pp, *Pl, *xph, *xlh, *Wh;
    int *cnt, *offs, *cur, *ssrc, *chs, *chb;
    cudaGetSymbolAddress((void**)&xpA, g_xpA);
    cudaGetSymbolAddress((void**)&xpB, g_xpB);
    cudaGetSymbolAddress((void**)&xlA, g_xlA);
    cudaGetSymbolAddress((void**)&xlB, g_xlB);
    cudaGetSymbolAddress((void**)&xph, g_xph);
    cudaGetSymbolAddress((void**)&xlh, g_xlh);
    cudaGetSymbolAddress((void**)&Wh, g_Wh);
    cudaGetSymbolAddress((void**)&Pp, g_Pp);
    cudaGetSymbolAddress((void**)&Pl, g_Pl);
    cudaGetSymbolAddress((void**)&Th, g_Th);
    cudaGetSymbolAddress((void**)&cnt, g_cnt);
    cudaGetSymbolAddress((void**)&offs, g_off);
    cudaGetSymbolAddress((void**)&cur, g_cur);
    cudaGetSymbolAddress((void**)&ssrc, g_ssrc);
    cudaGetSymbolAddress((void**)&su, g_su);
    cudaGetSymbolAddress((void**)&chs, g_chunksum);
    cudaGetSymbolAddress((void**)&chb, g_chunkbase);

    cudaFuncSetAttribute(proj_mma, cudaFuncAttributeMaxDynamicSharedMemorySize, SMEM_MMA_BYTES);

    embed_kernel<<<NP + NL, 128>>>(x_protein, Wp, bp, x_ligand, Wl, bl, xpA, xlA, xph, xlh);
    wconv<<<dim3(48, 128), 128>>>(Wf, Ws, Wh);
    lut_build<<<dim3(NBIN, 12), 256>>>(Wf, Ws, Th);
    cudaMemsetAsync(cnt, 0, NCNT * sizeof(int), 0);
    hist_all<<<(ETOT + 255) / 256, 256>>>(ei_pp, ei_lp, ei_pl, cnt);
    proj_mma<<<dim3((NP + 127) / 128, 12), 256, SMEM_MMA_BYTES>>>(xph, xlh, Wh, Pp, Pl);
    scanA<<<CHT, 1024>>>(cnt, offs, chs);
    scanB<<<1, 32>>>(chs, chb, offs);
    scanC<<<CHT, 1024>>>(offs, chb, cur);
    scatter_all<<<(ETOT + 255) / 256, 256>>>(ei_pp, ea_pp, ei_lp, ea_lp, ei_pl, ea_pl,
                                             cur, ssrc, su);

    float* xp_cur = xpA; float* xp_nxt = xpB;
    float* xl_cur = xlA; float* xl_nxt = xlB;

    for (int l = 0; l < NLAYER; ++l) {
        if (l > 0)
            proj_mma<<<dim3((NP + 127) / 128, 12), 256, SMEM_MMA_BYTES>>>(
                xph, xlh, Wh + (size_t)l * 12 * 128 * 128, Pp, Pl);

        FusedArgs fa;
        fa.off[0] = offs;              fa.ssrc[0] = ssrc;             fa.su[0] = su;
        fa.T[0] = Th + (size_t)(l * 3 + 0) * NBIN * 256;
        fa.Pd[0] = Pp + 0 * H; fa.dstr[0] = 8 * H;
        fa.Ps[0] = Pp + 2 * H; fa.sstr[0] = 8 * H;
        fa.bfp[0] = bf + (size_t)(l * 3 + 0) * H; fa.bsp[0] = bs + (size_t)(l * 3 + 0) * H;
        fa.off[1] = offs + NP + 1;     fa.ssrc[1] = ssrc + EPP;       fa.su[1] = su + EPP;
        fa.T[1] = Th + (size_t)(l * 3 + 1) * NBIN * 256;
        fa.Pd[1] = Pp + 4 * H; fa.dstr[1] = 8 * H;
        fa.Ps[1] = Pl + 0 * H; fa.sstr[1] = 4 * H;
        fa.bfp[1] = bf + (size_t)(l * 3 + 1) * H; fa.bsp[1] = bs + (size_t)(l * 3 + 1) * H;
        fa.off[2] = offs + 2 * NP + 2; fa.ssrc[2] = ssrc + EPP + ELP; fa.su[2] = su + EPP + ELP;
        fa.T[2] = Th + (size_t)(l * 3 + 2) * NBIN * 256;
        fa.Pd[2] = Pl + 2 * H; fa.dstr[2] = 4 * H;
        fa.Ps[2] = Pp + 6 * H; fa.sstr[2] = 8 * H;
        fa.bfp[2] = bf + (size_t)(l * 3 + 2) * H; fa.bsp[2] = bs + (size_t)(l * 3 + 2) * H;
        fa.bn_w = bn_w; fa.bn_b = bn_b; fa.ln_w = ln_w; fa.ln_b = ln_b;
        fa.layer = l;
        fa.xp_in = xp_cur; fa.xl_in = xl_cur;
        fa.xp_out = xp_nxt; fa.xl_out = xl_nxt;
        fa.xph_out = xph; fa.xlh_out = xlh;

        edge_update<<<(NP + NL + 7) / 8, 256>>>(fa);

        float* t;
        t = xp_cur; xp_cur = xp_nxt; xp_nxt = t;
        t = xl_cur; xl_cur = xl_nxt; xl_nxt = t;
    }

    final_kernel<<<(NP + 7) / 8, 256>>>(xp_cur, lno_w, lno_b, fc_w, fc_b, out);
}